// round 1
// baseline (speedup 1.0000x reference)
#include <cuda_runtime.h>
#include <math.h>

#define BATCH 8
#define CH 128
#define NTOK 4096
#define NGRP 32
#define CPG 4
#define GN_EPS 1e-5f

// ---------------- scratch (device globals; no allocations) ----------------
__device__ float g_xd[BATCH * CH * NTOK];   // group-normed x, (b, c, n) channel-major
__device__ float g_q [BATCH * NTOK * CH];   // (b, n, c) token-major
__device__ float g_k [BATCH * NTOK * CH];
__device__ float g_v [BATCH * NTOK * CH];
__device__ float g_ao[BATCH * NTOK * CH];   // attention output, token-major

// ======================= K1: GroupNorm =======================
// one block per (b, g). group = 4 contiguous channels * 4096 = 16384 contiguous floats.
__global__ __launch_bounds__(256) void gn_kernel(const float* __restrict__ x,
                                                 const float* __restrict__ gw,
                                                 const float* __restrict__ gb) {
    int bg = blockIdx.x;
    int b = bg >> 5, g = bg & 31;
    size_t base = (size_t)(b * CH + g * CPG) * NTOK;
    const float4* xv = (const float4*)(x + base);
    float4* ov = (float4*)(g_xd + base);
    int tid = threadIdx.x;

    float4 loc[16];
    float s = 0.f, ss = 0.f;
#pragma unroll
    for (int r = 0; r < 16; r++) {
        float4 v = xv[tid + r * 256];
        loc[r] = v;
        s  += v.x + v.y + v.z + v.w;
        ss += v.x * v.x + v.y * v.y + v.z * v.z + v.w * v.w;
    }
    __shared__ float rs[8], rss[8];
#pragma unroll
    for (int o = 16; o; o >>= 1) {
        s  += __shfl_xor_sync(0xffffffffu, s, o);
        ss += __shfl_xor_sync(0xffffffffu, ss, o);
    }
    if ((tid & 31) == 0) { rs[tid >> 5] = s; rss[tid >> 5] = ss; }
    __syncthreads();
    if (tid < 32) {
        s  = (tid < 8) ? rs[tid]  : 0.f;
        ss = (tid < 8) ? rss[tid] : 0.f;
#pragma unroll
        for (int o = 4; o; o >>= 1) {
            s  += __shfl_xor_sync(0xffffffffu, s, o);
            ss += __shfl_xor_sync(0xffffffffu, ss, o);
        }
        if (tid == 0) { rs[0] = s; rss[0] = ss; }
    }
    __syncthreads();
    const float invN = 1.f / (CPG * NTOK);
    float mean = rs[0] * invN;
    float var  = rss[0] * invN - mean * mean;
    float rinv = rsqrtf(var + GN_EPS);

#pragma unroll
    for (int r = 0; r < 16; r++) {
        int idx = tid + r * 256;
        int c = g * CPG + ((idx * 4) >> 12);
        float a = gw[c] * rinv;
        float bb = gb[c] - mean * a;
        float4 v = loc[r];
        v.x = v.x * a + bb; v.y = v.y * a + bb;
        v.z = v.z * a + bb; v.w = v.w * a + bb;
        ov[idx] = v;
    }
}

// ======================= K2: fused QKV projection =======================
// grid (64 token-tiles, 8 batches, 3 projections); out[b][n][o] = sum_c W[o][c] xd[b][c][n] + bias[o]
__global__ __launch_bounds__(256) void qkv_kernel(const float* __restrict__ wq, const float* __restrict__ bq,
                                                  const float* __restrict__ wk, const float* __restrict__ bk,
                                                  const float* __restrict__ wv, const float* __restrict__ bv) {
    int p = blockIdx.z, b = blockIdx.y, n0 = blockIdx.x * 64;
    const float* W    = (p == 0) ? wq : (p == 1) ? wk : wv;
    const float* bias = (p == 0) ? bq : (p == 1) ? bk : bv;
    float* out        = (p == 0) ? g_q : (p == 1) ? g_k : g_v;

    __shared__ float ws[32 * 132];  // ws[cc][o], transposed W chunk
    __shared__ float xs[32 * 68];   // xs[cc][t]

    int tid = threadIdx.x, tr = tid >> 4, tc = tid & 15;
    float acc[4][8];
#pragma unroll
    for (int t = 0; t < 4; t++)
#pragma unroll
        for (int o = 0; o < 8; o++) acc[t][o] = 0.f;

    const float* xb = g_xd + (size_t)b * CH * NTOK + n0;

    for (int c0 = 0; c0 < 128; c0 += 32) {
        __syncthreads();
#pragma unroll
        for (int r = 0; r < 16; r++) {          // 128*32 / 256
            int idx = tid + r * 256;
            int o = idx >> 5, cc = idx & 31;    // coalesced global read along cc
            ws[cc * 132 + o] = W[o * 128 + c0 + cc];
        }
#pragma unroll
        for (int r = 0; r < 8; r++) {           // 32*64 / 256
            int idx = tid + r * 256;
            int cc = idx >> 6, t = idx & 63;    // coalesced along t
            xs[cc * 68 + t] = xb[(size_t)(c0 + cc) * NTOK + t];
        }
        __syncthreads();
#pragma unroll 8
        for (int cc = 0; cc < 32; cc++) {
            float4 xv = *(float4*)&xs[cc * 68 + tr * 4];
            float4 wa = *(float4*)&ws[cc * 132 + tc * 8];
            float4 wb = *(float4*)&ws[cc * 132 + tc * 8 + 4];
            float xt[4] = {xv.x, xv.y, xv.z, xv.w};
            float w8[8] = {wa.x, wa.y, wa.z, wa.w, wb.x, wb.y, wb.z, wb.w};
#pragma unroll
            for (int t = 0; t < 4; t++)
#pragma unroll
                for (int o = 0; o < 8; o++) acc[t][o] += xt[t] * w8[o];
        }
    }

    float4 b0 = *(const float4*)&bias[tc * 8];
    float4 b1 = *(const float4*)&bias[tc * 8 + 4];
#pragma unroll
    for (int t = 0; t < 4; t++) {
        int n = n0 + tr * 4 + t;
        float* dst = out + ((size_t)b * NTOK + n) * CH + tc * 8;
        float4 o0, o1;
        o0.x = acc[t][0] + b0.x; o0.y = acc[t][1] + b0.y;
        o0.z = acc[t][2] + b0.z; o0.w = acc[t][3] + b0.w;
        o1.x = acc[t][4] + b1.x; o1.y = acc[t][5] + b1.y;
        o1.z = acc[t][6] + b1.z; o1.w = acc[t][7] + b1.w;
        *(float4*)dst = o0;
        *(float4*)(dst + 4) = o1;
    }
}

// ======================= K3: flash attention =======================
// grid (64 q-tiles, 8 batches), 256 threads, BQ=BK=64, head dim 128.
#define QKP 68                       // padded transposed row stride (floats)
#define SM_QS 0
#define SM_KS (128 * QKP)
#define SM_VS (2 * 128 * QKP)
#define SM_PT (2 * 128 * QKP + 64 * 128)
#define ATTN_SMEM ((2 * 128 * QKP + 64 * 128 + 64 * QKP) * 4)

__global__ __launch_bounds__(256, 1) void attn_kernel() {
    extern __shared__ float sm[];
    float* Qs = sm + SM_QS;   // [128][QKP]  Qs[c][i], pre-scaled by 1/sqrt(128)
    float* Ks = sm + SM_KS;   // [128][QKP]  Ks[c][j]
    float* Vs = sm + SM_VS;   // [64][128]   Vs[j][cc]
    float* Pt = sm + SM_PT;   // [64][QKP]   Pt[j][i]

    int b = blockIdx.y;
    int n0 = blockIdx.x * 64;
    int tid = threadIdx.x, tr = tid >> 4, tc = tid & 15;
    const float scale = 0.08838834764831845f;  // 1/sqrt(128)

    const float* qb = g_q + ((size_t)b * NTOK + n0) * CH;
    const float* kb = g_k + (size_t)b * NTOK * CH;
    const float* vb = g_v + (size_t)b * NTOK * CH;

    // load Q tile transposed + scaled (coalesced reads, stride-68 stores)
    for (int idx = tid; idx < 64 * 128; idx += 256) {
        int i = idx >> 7, c = idx & 127;
        Qs[c * QKP + i] = qb[idx] * scale;
    }

    float m[4], l[4], acc[4][8];
#pragma unroll
    for (int r = 0; r < 4; r++) {
        m[r] = -INFINITY; l[r] = 0.f;
#pragma unroll
        for (int cc = 0; cc < 8; cc++) acc[r][cc] = 0.f;
    }

    for (int j0 = 0; j0 < NTOK; j0 += 64) {
        __syncthreads();  // protect Ks/Vs/Pt from previous iteration readers
        for (int idx = tid; idx < 64 * 128; idx += 256) {
            int jj = idx >> 7, c = idx & 127;
            Ks[c * QKP + jj] = kb[(size_t)(j0 + jj) * CH + c];
        }
        {
            const float4* src = (const float4*)(vb + (size_t)j0 * CH);
            float4* dst = (float4*)Vs;
            for (int idx = tid; idx < 64 * 128 / 4; idx += 256) dst[idx] = src[idx];
        }
        __syncthreads();

        // ---- S = Q K^T ----
        float s[4][4];
#pragma unroll
        for (int r = 0; r < 4; r++)
#pragma unroll
            for (int j = 0; j < 4; j++) s[r][j] = 0.f;

        int qi = tr * 4, kj = tc * 4;
#pragma unroll 8
        for (int c = 0; c < 128; c++) {
            float4 q4 = *(float4*)&Qs[c * QKP + qi];
            float4 k4 = *(float4*)&Ks[c * QKP + kj];
            float qv[4] = {q4.x, q4.y, q4.z, q4.w};
            float kv[4] = {k4.x, k4.y, k4.z, k4.w};
#pragma unroll
            for (int r = 0; r < 4; r++)
#pragma unroll
                for (int j = 0; j < 4; j++) s[r][j] += qv[r] * kv[j];
        }

        // ---- online softmax (rows owned by the 16 threads sharing tr) ----
#pragma unroll
        for (int r = 0; r < 4; r++) {
            float tm = fmaxf(fmaxf(s[r][0], s[r][1]), fmaxf(s[r][2], s[r][3]));
#pragma unroll
            for (int o = 1; o < 16; o <<= 1) tm = fmaxf(tm, __shfl_xor_sync(0xffffffffu, tm, o));
            float mnew = fmaxf(m[r], tm);
            float alpha = __expf(m[r] - mnew);
            float ts = 0.f;
#pragma unroll
            for (int j = 0; j < 4; j++) {
                float pv = __expf(s[r][j] - mnew);
                s[r][j] = pv;
                ts += pv;
            }
#pragma unroll
            for (int o = 1; o < 16; o <<= 1) ts += __shfl_xor_sync(0xffffffffu, ts, o);
            l[r] = l[r] * alpha + ts;
            m[r] = mnew;
#pragma unroll
            for (int cc = 0; cc < 8; cc++) acc[r][cc] *= alpha;
#pragma unroll
            for (int j = 0; j < 4; j++) Pt[(tc * 4 + j) * QKP + tr * 4 + r] = s[r][j];
        }
        __syncthreads();

        // ---- O += P V ----
#pragma unroll 4
        for (int j = 0; j < 64; j++) {
            float4 p4 = *(float4*)&Pt[j * QKP + tr * 4];
            float4 va = *(float4*)&Vs[j * 128 + tc * 8];
            float4 vbv = *(float4*)&Vs[j * 128 + tc * 8 + 4];
            float pv[4] = {p4.x, p4.y, p4.z, p4.w};
            float v8[8] = {va.x, va.y, va.z, va.w, vbv.x, vbv.y, vbv.z, vbv.w};
#pragma unroll
            for (int r = 0; r < 4; r++)
#pragma unroll
                for (int cc = 0; cc < 8; cc++) acc[r][cc] += pv[r] * v8[cc];
        }
    }

    // finalize: divide by l, write token-major
#pragma unroll
    for (int r = 0; r < 4; r++) {
        float inv = 1.f / l[r];
        float* dst = g_ao + ((size_t)b * NTOK + n0 + tr * 4 + r) * CH + tc * 8;
        float4 o0, o1;
        o0.x = acc[r][0] * inv; o0.y = acc[r][1] * inv;
        o0.z = acc[r][2] * inv; o0.w = acc[r][3] * inv;
        o1.x = acc[r][4] * inv; o1.y = acc[r][5] * inv;
        o1.z = acc[r][6] * inv; o1.w = acc[r][7] * inv;
        *(float4*)dst = o0;
        *(float4*)(dst + 4) = o1;
    }
}

// ======================= K4: output projection + residual =======================
// out[b][o][n] = x[b][o][n] + gamma * (sum_c Wo[o][c] ao[b][n][c] + bo[o])
__global__ __launch_bounds__(256) void out_kernel(const float* __restrict__ x,
                                                  const float* __restrict__ wo,
                                                  const float* __restrict__ bo,
                                                  const float* __restrict__ gamma,
                                                  float* __restrict__ out) {
    int b = blockIdx.y, n0 = blockIdx.x * 64;
    __shared__ float ws[32 * 132];  // ws[cc][o]
    __shared__ float as_[32 * 68];  // as_[cc][t]
    int tid = threadIdx.x, tr = tid >> 4, tc = tid & 15;

    float acc[8][4];
#pragma unroll
    for (int oo = 0; oo < 8; oo++)
#pragma unroll
        for (int nn = 0; nn < 4; nn++) acc[oo][nn] = 0.f;

    const float* aob = g_ao + ((size_t)b * NTOK + n0) * CH;

    for (int c0 = 0; c0 < 128; c0 += 32) {
        __syncthreads();
#pragma unroll
        for (int r = 0; r < 16; r++) {
            int idx = tid + r * 256;
            int o = idx >> 5, cc = idx & 31;
            ws[cc * 132 + o] = wo[o * 128 + c0 + cc];
        }
#pragma unroll
        for (int r = 0; r < 8; r++) {
            int idx = tid + r * 256;
            int t = idx >> 5, cc = idx & 31;   // coalesced along cc
            as_[cc * 68 + t] = aob[(size_t)t * CH + c0 + cc];
        }
        __syncthreads();
#pragma unroll 8
        for (int cc = 0; cc < 32; cc++) {
            float4 a4 = *(float4*)&as_[cc * 68 + tc * 4];
            float4 w0 = *(float4*)&ws[cc * 132 + tr * 8];
            float4 w1 = *(float4*)&ws[cc * 132 + tr * 8 + 4];
            float an[4] = {a4.x, a4.y, a4.z, a4.w};
            float w8[8] = {w0.x, w0.y, w0.z, w0.w, w1.x, w1.y, w1.z, w1.w};
#pragma unroll
            for (int oo = 0; oo < 8; oo++)
#pragma unroll
                for (int nn = 0; nn < 4; nn++) acc[oo][nn] += w8[oo] * an[nn];
        }
    }

    float gma = gamma[0];
#pragma unroll
    for (int oo = 0; oo < 8; oo++) {
        int o = tr * 8 + oo;
        float bv = bo[o];
        size_t idx = ((size_t)(b * CH + o)) * NTOK + n0 + tc * 4;
        float4 xr = *(const float4*)&x[idx];
        float4 o4;
        o4.x = xr.x + gma * (acc[oo][0] + bv);
        o4.y = xr.y + gma * (acc[oo][1] + bv);
        o4.z = xr.z + gma * (acc[oo][2] + bv);
        o4.w = xr.w + gma * (acc[oo][3] + bv);
        *(float4*)&out[idx] = o4;
    }
}

// ======================= launch =======================
extern "C" void kernel_launch(void* const* d_in, const int* in_sizes, int n_in,
                              void* d_out, int out_size) {
    const float* x  = (const float*)d_in[0];
    const float* gw = (const float*)d_in[1];
    const float* gb = (const float*)d_in[2];
    const float* wq = (const float*)d_in[3];
    const float* bq = (const float*)d_in[4];
    const float* wk = (const float*)d_in[5];
    const float* bk = (const float*)d_in[6];
    const float* wv = (const float*)d_in[7];
    const float* bv = (const float*)d_in[8];
    const float* wo = (const float*)d_in[9];
    const float* bo = (const float*)d_in[10];
    const float* gamma = (const float*)d_in[11];
    float* out = (float*)d_out;

    static bool attr_set = false;
    if (!attr_set) {
        cudaFuncSetAttribute(attn_kernel, cudaFuncAttributeMaxDynamicSharedMemorySize, ATTN_SMEM);
        attr_set = true;
    }

    gn_kernel<<<BATCH * NGRP, 256>>>(x, gw, gb);
    qkv_kernel<<<dim3(NTOK / 64, BATCH, 3), 256>>>(wq, bq, wk, bk, wv, bv);
    attn_kernel<<<dim3(NTOK / 64, BATCH), 256, ATTN_SMEM>>>();
    out_kernel<<<dim3(NTOK / 64, BATCH), 256>>>(x, wo, bo, gamma, out);
}

// round 3
// speedup vs baseline: 4.0091x; 4.0091x over previous
#include <cuda_runtime.h>
#include <math.h>
#include <stdint.h>

#define BATCH 8
#define CH 128
#define NTOK 4096
#define NGRP 32
#define CPG 4
#define GN_EPS 1e-5f
#define QK_SCALE 0.08838834764831845f  // 1/sqrt(128)

// ---------------- scratch (device globals; no allocations) ----------------
__device__ float g_xd[BATCH * CH * NTOK];   // group-normed x, (b, c, n) channel-major
__device__ float g_q [BATCH * NTOK * CH];   // (b, n, c) token-major, prescaled + tf32-rounded
__device__ float g_k [BATCH * NTOK * CH];   // (b, n, c) token-major, tf32-rounded
__device__ float g_v [BATCH * NTOK * CH];   // (b, n, c) token-major, tf32-rounded
__device__ float g_ao[BATCH * NTOK * CH];   // attention output, token-major, fp32

// ======================= helpers =======================
__device__ __forceinline__ uint32_t smem_u32(const void* p) {
    uint32_t a;
    asm("{ .reg .u64 t; cvta.to.shared.u64 t, %1; cvt.u32.u64 %0, t; }" : "=r"(a) : "l"(p));
    return a;
}
__device__ __forceinline__ float tf32r(float x) {
    uint32_t u;
    asm("cvt.rna.tf32.f32 %0, %1;" : "=r"(u) : "f"(x));
    return __uint_as_float(u);
}
__device__ __forceinline__ uint32_t tf32u(float x) {
    uint32_t u;
    asm("cvt.rna.tf32.f32 %0, %1;" : "=r"(u) : "f"(x));
    return u;
}
// D += A * B  (m16n8k8, tf32 in, fp32 accum). A row-major m16xk8, B col-major k8xn8.
__device__ __forceinline__ void mma_tf32(float* d, uint32_t a0, uint32_t a1, uint32_t a2, uint32_t a3,
                                         uint32_t b0, uint32_t b1) {
    asm volatile(
        "mma.sync.aligned.m16n8k8.row.col.f32.tf32.tf32.f32 "
        "{%0,%1,%2,%3}, {%4,%5,%6,%7}, {%8,%9}, {%0,%1,%2,%3};"
        : "+f"(d[0]), "+f"(d[1]), "+f"(d[2]), "+f"(d[3])
        : "r"(a0), "r"(a1), "r"(a2), "r"(a3), "r"(b0), "r"(b1));
}
#define CP_ASYNC16(dst_u32, src_ptr) \
    asm volatile("cp.async.cg.shared.global [%0], [%1], 16;" :: "r"(dst_u32), "l"(src_ptr))
#define CP_COMMIT()  asm volatile("cp.async.commit_group;" ::: "memory")
#define CP_WAIT1()   asm volatile("cp.async.wait_group 1;" ::: "memory")

// ======================= K1: GroupNorm =======================
__global__ __launch_bounds__(256) void gn_kernel(const float* __restrict__ x,
                                                 const float* __restrict__ gw,
                                                 const float* __restrict__ gb) {
    int bg = blockIdx.x;
    int b = bg >> 5, g = bg & 31;
    size_t base = (size_t)(b * CH + g * CPG) * NTOK;
    const float4* xv = (const float4*)(x + base);
    float4* ov = (float4*)(g_xd + base);
    int tid = threadIdx.x;

    float4 loc[16];
    float s = 0.f, ss = 0.f;
#pragma unroll
    for (int r = 0; r < 16; r++) {
        float4 v = xv[tid + r * 256];
        loc[r] = v;
        s  += v.x + v.y + v.z + v.w;
        ss += v.x * v.x + v.y * v.y + v.z * v.z + v.w * v.w;
    }
    __shared__ float rs[8], rss[8];
#pragma unroll
    for (int o = 16; o; o >>= 1) {
        s  += __shfl_xor_sync(0xffffffffu, s, o);
        ss += __shfl_xor_sync(0xffffffffu, ss, o);
    }
    if ((tid & 31) == 0) { rs[tid >> 5] = s; rss[tid >> 5] = ss; }
    __syncthreads();
    if (tid < 32) {
        s  = (tid < 8) ? rs[tid]  : 0.f;
        ss = (tid < 8) ? rss[tid] : 0.f;
#pragma unroll
        for (int o = 4; o; o >>= 1) {
            s  += __shfl_xor_sync(0xffffffffu, s, o);
            ss += __shfl_xor_sync(0xffffffffu, ss, o);
        }
        if (tid == 0) { rs[0] = s; rss[0] = ss; }
    }
    __syncthreads();
    const float invN = 1.f / (CPG * NTOK);
    float mean = rs[0] * invN;
    float var  = rss[0] * invN - mean * mean;
    float rinv = rsqrtf(var + GN_EPS);

#pragma unroll
    for (int r = 0; r < 16; r++) {
        int idx = tid + r * 256;
        int c = g * CPG + ((idx * 4) >> 12);
        float a = gw[c] * rinv;
        float bb = gb[c] - mean * a;
        float4 v = loc[r];
        v.x = v.x * a + bb; v.y = v.y * a + bb;
        v.z = v.z * a + bb; v.w = v.w * a + bb;
        ov[idx] = v;
    }
}

// ======================= K2: fused QKV projection =======================
// Q scaled by 1/sqrt(128); Q,K,V tf32-rounded for the attention MMAs.
__global__ __launch_bounds__(256) void qkv_kernel(const float* __restrict__ wq, const float* __restrict__ bq,
                                                  const float* __restrict__ wk, const float* __restrict__ bk,
                                                  const float* __restrict__ wv, const float* __restrict__ bv) {
    int p = blockIdx.z, b = blockIdx.y, n0 = blockIdx.x * 64;
    const float* W    = (p == 0) ? wq : (p == 1) ? wk : wv;
    const float* bias = (p == 0) ? bq : (p == 1) ? bk : bv;
    float* out        = (p == 0) ? g_q : (p == 1) ? g_k : g_v;
    float postscale   = (p == 0) ? QK_SCALE : 1.0f;

    __shared__ float ws[32 * 132];
    __shared__ float xs[32 * 68];

    int tid = threadIdx.x, tr = tid >> 4, tc = tid & 15;
    float acc[4][8];
#pragma unroll
    for (int t = 0; t < 4; t++)
#pragma unroll
        for (int o = 0; o < 8; o++) acc[t][o] = 0.f;

    const float* xb = g_xd + (size_t)b * CH * NTOK + n0;

    for (int c0 = 0; c0 < 128; c0 += 32) {
        __syncthreads();
#pragma unroll
        for (int r = 0; r < 16; r++) {
            int idx = tid + r * 256;
            int o = idx >> 5, cc = idx & 31;
            ws[cc * 132 + o] = W[o * 128 + c0 + cc];
        }
#pragma unroll
        for (int r = 0; r < 8; r++) {
            int idx = tid + r * 256;
            int cc = idx >> 6, t = idx & 63;
            xs[cc * 68 + t] = xb[(size_t)(c0 + cc) * NTOK + t];
        }
        __syncthreads();
#pragma unroll 8
        for (int cc = 0; cc < 32; cc++) {
            float4 xv = *(float4*)&xs[cc * 68 + tr * 4];
            float4 wa = *(float4*)&ws[cc * 132 + tc * 8];
            float4 wb = *(float4*)&ws[cc * 132 + tc * 8 + 4];
            float xt[4] = {xv.x, xv.y, xv.z, xv.w};
            float w8[8] = {wa.x, wa.y, wa.z, wa.w, wb.x, wb.y, wb.z, wb.w};
#pragma unroll
            for (int t = 0; t < 4; t++)
#pragma unroll
                for (int o = 0; o < 8; o++) acc[t][o] += xt[t] * w8[o];
        }
    }

    float bb[8];
#pragma unroll
    for (int o = 0; o < 8; o++) bb[o] = bias[tc * 8 + o];

#pragma unroll
    for (int t = 0; t < 4; t++) {
        int n = n0 + tr * 4 + t;
        float* dst = out + ((size_t)b * NTOK + n) * CH + tc * 8;
        float4 o0, o1;
        o0.x = tf32r((acc[t][0] + bb[0]) * postscale);
        o0.y = tf32r((acc[t][1] + bb[1]) * postscale);
        o0.z = tf32r((acc[t][2] + bb[2]) * postscale);
        o0.w = tf32r((acc[t][3] + bb[3]) * postscale);
        o1.x = tf32r((acc[t][4] + bb[4]) * postscale);
        o1.y = tf32r((acc[t][5] + bb[5]) * postscale);
        o1.z = tf32r((acc[t][6] + bb[6]) * postscale);
        o1.w = tf32r((acc[t][7] + bb[7]) * postscale);
        *(float4*)dst = o0;
        *(float4*)(dst + 4) = o1;
    }
}

// ======================= K3: mma.sync tf32 flash attention =======================
// BQ=128 per CTA (8 warps x 16 rows), BK=64 key tiles, double-buffered cp.async.
#define QSTRIDE 132
#define Q_FLOATS (128 * QSTRIDE)            // 16896
#define KV_FLOATS (64 * QSTRIDE)            // 8448
#define OFF_K0 Q_FLOATS
#define OFF_K1 (Q_FLOATS + KV_FLOATS)
#define OFF_V0 (Q_FLOATS + 2 * KV_FLOATS)
#define OFF_V1 (Q_FLOATS + 3 * KV_FLOATS)
#define ATTN_SMEM ((Q_FLOATS + 4 * KV_FLOATS) * 4)   // 202752 B

__global__ __launch_bounds__(256, 1) void attn_mma_kernel() {
    extern __shared__ float smf[];
    uint32_t sbase = smem_u32(smf);
    int tid = threadIdx.x;
    int w = tid >> 5, lid = tid & 31;
    int gr = lid >> 2, t = lid & 3;
    int r0 = w * 16;
    int b = blockIdx.y, n0 = blockIdx.x * 128;

    const float* qg = g_q + ((size_t)b * NTOK + n0) * CH;
    const float* kg = g_k + (size_t)b * NTOK * CH;
    const float* vg = g_v + (size_t)b * NTOK * CH;

    // ---- prologue: Q + first two K/V tiles via cp.async ----
    {
        // Q: 128 rows x 128 floats -> 4096 float4
#pragma unroll
        for (int r = 0; r < 16; r++) {
            int idx = tid + r * 256;
            int row = idx >> 5, seg = idx & 31;
            CP_ASYNC16(sbase + (uint32_t)(row * QSTRIDE + seg * 4) * 4, qg + row * CH + seg * 4);
        }
        // tile 0 K/V
#pragma unroll
        for (int r = 0; r < 8; r++) {
            int idx = tid + r * 256;
            int row = idx >> 5, seg = idx & 31;
            CP_ASYNC16(sbase + (uint32_t)(OFF_K0 + row * QSTRIDE + seg * 4) * 4, kg + row * CH + seg * 4);
            CP_ASYNC16(sbase + (uint32_t)(OFF_V0 + row * QSTRIDE + seg * 4) * 4, vg + row * CH + seg * 4);
        }
        CP_COMMIT();  // group 0: Q + tile0
        // tile 1 K/V
#pragma unroll
        for (int r = 0; r < 8; r++) {
            int idx = tid + r * 256;
            int row = idx >> 5, seg = idx & 31;
            CP_ASYNC16(sbase + (uint32_t)(OFF_K1 + row * QSTRIDE + seg * 4) * 4,
                       kg + (size_t)(64 + row) * CH + seg * 4);
            CP_ASYNC16(sbase + (uint32_t)(OFF_V1 + row * QSTRIDE + seg * 4) * 4,
                       vg + (size_t)(64 + row) * CH + seg * 4);
        }
        CP_COMMIT();  // group 1: tile1
    }

    const uint32_t* Qu = (const uint32_t*)smf;
    float oacc[16][4];
#pragma unroll
    for (int v = 0; v < 16; v++)
#pragma unroll
        for (int i = 0; i < 4; i++) oacc[v][i] = 0.f;
    float l0 = 0.f, l1 = 0.f;

    for (int tl = 0; tl < NTOK / 64; tl++) {
        CP_WAIT1();
        __syncthreads();

        int buf = tl & 1;
        const uint32_t* Ku = (const uint32_t*)(smf + (buf ? OFF_K1 : OFF_K0));
        const uint32_t* Vu = (const uint32_t*)(smf + (buf ? OFF_V1 : OFF_V0));

        // ---- S = Q K^T : per warp 16 x 64 ----
        float sacc[8][4];
#pragma unroll
        for (int n = 0; n < 8; n++)
#pragma unroll
            for (int i = 0; i < 4; i++) sacc[n][i] = 0.f;

#pragma unroll
        for (int k = 0; k < 16; k++) {
            uint32_t a0 = Qu[(r0 + gr) * QSTRIDE + k * 8 + t];
            uint32_t a1 = Qu[(r0 + gr + 8) * QSTRIDE + k * 8 + t];
            uint32_t a2 = Qu[(r0 + gr) * QSTRIDE + k * 8 + t + 4];
            uint32_t a3 = Qu[(r0 + gr + 8) * QSTRIDE + k * 8 + t + 4];
#pragma unroll
            for (int n = 0; n < 8; n++) {
                uint32_t b0 = Ku[(n * 8 + gr) * QSTRIDE + k * 8 + t];
                uint32_t b1 = Ku[(n * 8 + gr) * QSTRIDE + k * 8 + t + 4];
                mma_tf32(sacc[n], a0, a1, a2, a3, b0, b1);
            }
        }

        // ---- P = exp(S) (tf32-rounded), accumulate row sums ----
        uint32_t e[8][4];
#pragma unroll
        for (int n = 0; n < 8; n++) {
            uint32_t e0 = tf32u(__expf(sacc[n][0]));
            uint32_t e1 = tf32u(__expf(sacc[n][1]));
            uint32_t e2 = tf32u(__expf(sacc[n][2]));
            uint32_t e3 = tf32u(__expf(sacc[n][3]));
            e[n][0] = e0; e[n][1] = e1; e[n][2] = e2; e[n][3] = e3;
            l0 += __uint_as_float(e0) + __uint_as_float(e1);
            l1 += __uint_as_float(e2) + __uint_as_float(e3);
        }

        // ---- O += P V : per warp 16 x 128, k over 64 keys ----
        int src1 = (lid & 28) | (t >> 1);
        int src2 = src1 + 2;
        bool odd = t & 1;
#pragma unroll
        for (int u = 0; u < 8; u++) {
            uint32_t p00 = __shfl_sync(0xffffffffu, e[u][0], src1);
            uint32_t p01 = __shfl_sync(0xffffffffu, e[u][1], src1);
            uint32_t p02 = __shfl_sync(0xffffffffu, e[u][0], src2);
            uint32_t p03 = __shfl_sync(0xffffffffu, e[u][1], src2);
            uint32_t p10 = __shfl_sync(0xffffffffu, e[u][2], src1);
            uint32_t p11 = __shfl_sync(0xffffffffu, e[u][3], src1);
            uint32_t p12 = __shfl_sync(0xffffffffu, e[u][2], src2);
            uint32_t p13 = __shfl_sync(0xffffffffu, e[u][3], src2);
            uint32_t a0 = odd ? p01 : p00;
            uint32_t a2 = odd ? p03 : p02;
            uint32_t a1 = odd ? p11 : p10;
            uint32_t a3 = odd ? p13 : p12;
#pragma unroll
            for (int v = 0; v < 16; v++) {
                uint32_t b0 = Vu[(u * 8 + t) * QSTRIDE + v * 8 + gr];
                uint32_t b1 = Vu[(u * 8 + t + 4) * QSTRIDE + v * 8 + gr];
                mma_tf32(oacc[v], a0, a1, a2, a3, b0, b1);
            }
        }

        __syncthreads();
        // issue tile tl+2 into the buffer we just finished
        if (tl + 2 < NTOK / 64) {
            const float* kn = kg + (size_t)(tl + 2) * 64 * CH;
            const float* vn = vg + (size_t)(tl + 2) * 64 * CH;
            uint32_t koff = buf ? OFF_K1 : OFF_K0;
            uint32_t voff = buf ? OFF_V1 : OFF_V0;
#pragma unroll
            for (int r = 0; r < 8; r++) {
                int idx = tid + r * 256;
                int row = idx >> 5, seg = idx & 31;
                CP_ASYNC16(sbase + (koff + (uint32_t)(row * QSTRIDE + seg * 4)) * 4, kn + row * CH + seg * 4);
                CP_ASYNC16(sbase + (voff + (uint32_t)(row * QSTRIDE + seg * 4)) * 4, vn + row * CH + seg * 4);
            }
        }
        CP_COMMIT();
    }

    // ---- finalize: row sums over lane quads, normalize, store ----
    l0 += __shfl_xor_sync(0xffffffffu, l0, 1);
    l0 += __shfl_xor_sync(0xffffffffu, l0, 2);
    l1 += __shfl_xor_sync(0xffffffffu, l1, 1);
    l1 += __shfl_xor_sync(0xffffffffu, l1, 2);
    float inv0 = 1.f / l0, inv1 = 1.f / l1;

    size_t row0 = (size_t)b * NTOK + n0 + r0 + gr;
    size_t row1 = row0 + 8;
#pragma unroll
    for (int v = 0; v < 16; v++) {
        float2 w0 = {oacc[v][0] * inv0, oacc[v][1] * inv0};
        float2 w1 = {oacc[v][2] * inv1, oacc[v][3] * inv1};
        *(float2*)&g_ao[row0 * CH + v * 8 + 2 * t] = w0;
        *(float2*)&g_ao[row1 * CH + v * 8 + 2 * t] = w1;
    }
}

// ======================= K4: output projection + residual =======================
__global__ __launch_bounds__(256) void out_kernel(const float* __restrict__ x,
                                                  const float* __restrict__ wo,
                                                  const float* __restrict__ bo,
                                                  const float* __restrict__ gamma,
                                                  float* __restrict__ out) {
    int b = blockIdx.y, n0 = blockIdx.x * 64;
    __shared__ float ws[32 * 132];
    __shared__ float as_[32 * 68];
    int tid = threadIdx.x, tr = tid >> 4, tc = tid & 15;

    float acc[8][4];
#pragma unroll
    for (int oo = 0; oo < 8; oo++)
#pragma unroll
        for (int nn = 0; nn < 4; nn++) acc[oo][nn] = 0.f;

    const float* aob = g_ao + ((size_t)b * NTOK + n0) * CH;

    for (int c0 = 0; c0 < 128; c0 += 32) {
        __syncthreads();
#pragma unroll
        for (int r = 0; r < 16; r++) {
            int idx = tid + r * 256;
            int o = idx >> 5, cc = idx & 31;
            ws[cc * 132 + o] = wo[o * 128 + c0 + cc];
        }
#pragma unroll
        for (int r = 0; r < 8; r++) {
            int idx = tid + r * 256;
            int t = idx >> 5, cc = idx & 31;
            as_[cc * 68 + t] = aob[(size_t)t * CH + c0 + cc];
        }
        __syncthreads();
#pragma unroll 8
        for (int cc = 0; cc < 32; cc++) {
            float4 a4 = *(float4*)&as_[cc * 68 + tc * 4];
            float4 w0 = *(float4*)&ws[cc * 132 + tr * 8];
            float4 w1 = *(float4*)&ws[cc * 132 + tr * 8 + 4];
            float an[4] = {a4.x, a4.y, a4.z, a4.w};
            float w8[8] = {w0.x, w0.y, w0.z, w0.w, w1.x, w1.y, w1.z, w1.w};
#pragma unroll
            for (int oo = 0; oo < 8; oo++)
#pragma unroll
                for (int nn = 0; nn < 4; nn++) acc[oo][nn] += w8[oo] * an[nn];
        }
    }

    float gma = gamma[0];
#pragma unroll
    for (int oo = 0; oo < 8; oo++) {
        int o = tr * 8 + oo;
        float bv = bo[o];
        size_t idx = ((size_t)(b * CH + o)) * NTOK + n0 + tc * 4;
        float4 xr = *(const float4*)&x[idx];
        float4 o4;
        o4.x = xr.x + gma * (acc[oo][0] + bv);
        o4.y = xr.y + gma * (acc[oo][1] + bv);
        o4.z = xr.z + gma * (acc[oo][2] + bv);
        o4.w = xr.w + gma * (acc[oo][3] + bv);
        *(float4*)&out[idx] = o4;
    }
}

// ======================= launch =======================
extern "C" void kernel_launch(void* const* d_in, const int* in_sizes, int n_in,
                              void* d_out, int out_size) {
    const float* x  = (const float*)d_in[0];
    const float* gw = (const float*)d_in[1];
    const float* gb = (const float*)d_in[2];
    const float* wq = (const float*)d_in[3];
    const float* bq = (const float*)d_in[4];
    const float* wk = (const float*)d_in[5];
    const float* bk = (const float*)d_in[6];
    const float* wv = (const float*)d_in[7];
    const float* bv = (const float*)d_in[8];
    const float* wo = (const float*)d_in[9];
    const float* bo = (const float*)d_in[10];
    const float* gamma = (const float*)d_in[11];
    float* out = (float*)d_out;

    static bool attr_set = false;
    if (!attr_set) {
        cudaFuncSetAttribute(attn_mma_kernel, cudaFuncAttributeMaxDynamicSharedMemorySize, ATTN_SMEM);
        attr_set = true;
    }

    gn_kernel<<<BATCH * NGRP, 256>>>(x, gw, gb);
    qkv_kernel<<<dim3(NTOK / 64, BATCH, 3), 256>>>(wq, bq, wk, bk, wv, bv);
    attn_mma_kernel<<<dim3(NTOK / 128, BATCH), 256, ATTN_SMEM>>>();
    out_kernel<<<dim3(NTOK / 64, BATCH), 256>>>(x, wo, bo, gamma, out);
}

// round 4
// speedup vs baseline: 7.7124x; 1.9237x over previous
#include <cuda_runtime.h>
#include <cuda_bf16.h>
#include <math.h>
#include <stdint.h>

#define BATCH 8
#define CH 128
#define NTOK 4096
#define NGRP 32
#define CPG 4
#define GN_EPS 1e-5f
#define QK_SCALE 0.08838834764831845f  // 1/sqrt(128)

// ---------------- scratch (device globals; no allocations) ----------------
__device__ float g_xd[BATCH * CH * NTOK];            // group-normed x, (b,c,n)
__device__ __nv_bfloat16 g_q[BATCH * NTOK * CH];     // (b,n,c) token-major, prescaled
__device__ __nv_bfloat16 g_k[BATCH * NTOK * CH];     // (b,n,c) token-major
__device__ __nv_bfloat16 g_v[BATCH * CH * NTOK];     // (b,c,n) CHANNEL-major (V^T tiles)
__device__ float g_ao[BATCH * NTOK * CH];            // attention output, token-major fp32

// ======================= helpers =======================
__device__ __forceinline__ uint32_t smem_u32(const void* p) {
    uint32_t a;
    asm("{ .reg .u64 t; cvta.to.shared.u64 t, %1; cvt.u32.u64 %0, t; }" : "=r"(a) : "l"(p));
    return a;
}
__device__ __forceinline__ uint32_t pack_bf16x2(float lo, float hi) {
    uint32_t r;
    asm("cvt.rn.bf16x2.f32 %0, %1, %2;" : "=r"(r) : "f"(hi), "f"(lo));
    return r;
}
// D += A*B, m16n8k16, bf16 in / fp32 accum. A row-major m16xk16, B col-major k16xn8.
__device__ __forceinline__ void mma_bf16(float* d, uint32_t a0, uint32_t a1, uint32_t a2, uint32_t a3,
                                         uint32_t b0, uint32_t b1) {
    asm volatile(
        "mma.sync.aligned.m16n8k16.row.col.f32.bf16.bf16.f32 "
        "{%0,%1,%2,%3}, {%4,%5,%6,%7}, {%8,%9}, {%0,%1,%2,%3};"
        : "+f"(d[0]), "+f"(d[1]), "+f"(d[2]), "+f"(d[3])
        : "r"(a0), "r"(a1), "r"(a2), "r"(a3), "r"(b0), "r"(b1));
}
#define CP_ASYNC16(dst_u32, src_ptr) \
    asm volatile("cp.async.cg.shared.global [%0], [%1], 16;" :: "r"(dst_u32), "l"(src_ptr))
#define CP_COMMIT()  asm volatile("cp.async.commit_group;" ::: "memory")
#define CP_WAIT1()   asm volatile("cp.async.wait_group 1;" ::: "memory")

// ======================= K1: GroupNorm =======================
__global__ __launch_bounds__(256) void gn_kernel(const float* __restrict__ x,
                                                 const float* __restrict__ gw,
                                                 const float* __restrict__ gb) {
    int bg = blockIdx.x;
    int b = bg >> 5, g = bg & 31;
    size_t base = (size_t)(b * CH + g * CPG) * NTOK;
    const float4* xv = (const float4*)(x + base);
    float4* ov = (float4*)(g_xd + base);
    int tid = threadIdx.x;

    float4 loc[16];
    float s = 0.f, ss = 0.f;
#pragma unroll
    for (int r = 0; r < 16; r++) {
        float4 v = xv[tid + r * 256];
        loc[r] = v;
        s  += v.x + v.y + v.z + v.w;
        ss += v.x * v.x + v.y * v.y + v.z * v.z + v.w * v.w;
    }
    __shared__ float rs[8], rss[8];
#pragma unroll
    for (int o = 16; o; o >>= 1) {
        s  += __shfl_xor_sync(0xffffffffu, s, o);
        ss += __shfl_xor_sync(0xffffffffu, ss, o);
    }
    if ((tid & 31) == 0) { rs[tid >> 5] = s; rss[tid >> 5] = ss; }
    __syncthreads();
    if (tid < 32) {
        s  = (tid < 8) ? rs[tid]  : 0.f;
        ss = (tid < 8) ? rss[tid] : 0.f;
#pragma unroll
        for (int o = 4; o; o >>= 1) {
            s  += __shfl_xor_sync(0xffffffffu, s, o);
            ss += __shfl_xor_sync(0xffffffffu, ss, o);
        }
        if (tid == 0) { rs[0] = s; rss[0] = ss; }
    }
    __syncthreads();
    const float invN = 1.f / (CPG * NTOK);
    float mean = rs[0] * invN;
    float var  = rss[0] * invN - mean * mean;
    float rinv = rsqrtf(var + GN_EPS);

#pragma unroll
    for (int r = 0; r < 16; r++) {
        int idx = tid + r * 256;
        int c = g * CPG + ((idx * 4) >> 12);
        float a = gw[c] * rinv;
        float bb = gb[c] - mean * a;
        float4 v = loc[r];
        v.x = v.x * a + bb; v.y = v.y * a + bb;
        v.z = v.z * a + bb; v.w = v.w * a + bb;
        ov[idx] = v;
    }
}

// ======================= K2: fused QKV projection (bf16 outputs) =======================
__global__ __launch_bounds__(256) void qkv_kernel(const float* __restrict__ wq, const float* __restrict__ bq,
                                                  const float* __restrict__ wk, const float* __restrict__ bk,
                                                  const float* __restrict__ wv, const float* __restrict__ bv) {
    int p = blockIdx.z, b = blockIdx.y, n0 = blockIdx.x * 64;
    const float* W    = (p == 0) ? wq : (p == 1) ? wk : wv;
    const float* bias = (p == 0) ? bq : (p == 1) ? bk : bv;
    float postscale   = (p == 0) ? QK_SCALE : 1.0f;

    __shared__ float ws[32 * 132];
    __shared__ float xs[32 * 68];

    int tid = threadIdx.x, tr = tid >> 4, tc = tid & 15;
    float acc[4][8];
#pragma unroll
    for (int t = 0; t < 4; t++)
#pragma unroll
        for (int o = 0; o < 8; o++) acc[t][o] = 0.f;

    const float* xb = g_xd + (size_t)b * CH * NTOK + n0;

    for (int c0 = 0; c0 < 128; c0 += 32) {
        __syncthreads();
#pragma unroll
        for (int r = 0; r < 16; r++) {
            int idx = tid + r * 256;
            int o = idx >> 5, cc = idx & 31;
            ws[cc * 132 + o] = W[o * 128 + c0 + cc];
        }
#pragma unroll
        for (int r = 0; r < 8; r++) {
            int idx = tid + r * 256;
            int cc = idx >> 6, t = idx & 63;
            xs[cc * 68 + t] = xb[(size_t)(c0 + cc) * NTOK + t];
        }
        __syncthreads();
#pragma unroll 8
        for (int cc = 0; cc < 32; cc++) {
            float4 xv = *(float4*)&xs[cc * 68 + tr * 4];
            float4 wa = *(float4*)&ws[cc * 132 + tc * 8];
            float4 wb = *(float4*)&ws[cc * 132 + tc * 8 + 4];
            float xt[4] = {xv.x, xv.y, xv.z, xv.w};
            float w8[8] = {wa.x, wa.y, wa.z, wa.w, wb.x, wb.y, wb.z, wb.w};
#pragma unroll
            for (int t = 0; t < 4; t++)
#pragma unroll
                for (int o = 0; o < 8; o++) acc[t][o] += xt[t] * w8[o];
        }
    }

    float bb[8];
#pragma unroll
    for (int o = 0; o < 8; o++) bb[o] = bias[tc * 8 + o];

    if (p == 2) {
        // V: channel-major bf16 (b, c, n); thread owns 8 channels x 4 tokens
#pragma unroll
        for (int oo = 0; oo < 8; oo++) {
            int o = tc * 8 + oo;
            uint2 pk;
            pk.x = pack_bf16x2(acc[0][oo] + bb[oo], acc[1][oo] + bb[oo]);
            pk.y = pack_bf16x2(acc[2][oo] + bb[oo], acc[3][oo] + bb[oo]);
            *(uint2*)&g_v[((size_t)(b * CH + o)) * NTOK + n0 + tr * 4] = pk;
        }
    } else {
        __nv_bfloat16* out = (p == 0) ? g_q : g_k;
#pragma unroll
        for (int t = 0; t < 4; t++) {
            int n = n0 + tr * 4 + t;
            uint4 pk;
            pk.x = pack_bf16x2((acc[t][0] + bb[0]) * postscale, (acc[t][1] + bb[1]) * postscale);
            pk.y = pack_bf16x2((acc[t][2] + bb[2]) * postscale, (acc[t][3] + bb[3]) * postscale);
            pk.z = pack_bf16x2((acc[t][4] + bb[4]) * postscale, (acc[t][5] + bb[5]) * postscale);
            pk.w = pack_bf16x2((acc[t][6] + bb[6]) * postscale, (acc[t][7] + bb[7]) * postscale);
            *(uint4*)&out[((size_t)b * NTOK + n) * CH + tc * 8] = pk;
        }
    }
}

// ======================= K3: mma.sync bf16 flash attention =======================
// BQ=128 per CTA (8 warps x 16 rows), BK=64 key tiles, double-buffered cp.async.
// Q fragments in registers. K tiles [64 key][136 bf16 pad]; V^T tiles [128 ch][72 bf16 pad].
#define KROW_U32 68                           // K row stride in uint32 (136 bf16 = 272 B)
#define VROW_U32 36                           // V^T row stride in uint32 (72 bf16 = 144 B)
#define KTILE_B (64 * 272)                    // 17408
#define VTILE_B (128 * 144)                   // 18432
#define OFF_K0 0
#define OFF_K1 KTILE_B
#define OFF_V0 (2 * KTILE_B)
#define OFF_V1 (2 * KTILE_B + VTILE_B)
#define ATTN_SMEM (2 * KTILE_B + 2 * VTILE_B) // 71680 B

__global__ __launch_bounds__(256, 2) void attn_mma_kernel() {
    extern __shared__ char smem[];
    uint32_t sbase = smem_u32(smem);
    int tid = threadIdx.x;
    int w = tid >> 5, lid = tid & 31;
    int gr = lid >> 2, t = lid & 3;
    int r0 = w * 16;
    int b = blockIdx.y, n0 = blockIdx.x * 128;

    const __nv_bfloat16* kg = g_k + (size_t)b * NTOK * CH;   // token-major
    const __nv_bfloat16* vg = g_v + (size_t)b * CH * NTOK;   // channel-major

    // ---- Q fragments: loop-invariant, resident in registers ----
    uint32_t qa[8][4];
    {
        const uint32_t* qu = (const uint32_t*)(g_q + ((size_t)b * NTOK + n0) * CH);
        int row0 = (r0 + gr) * 64, row1 = (r0 + gr + 8) * 64;
#pragma unroll
        for (int k = 0; k < 8; k++) {
            qa[k][0] = qu[row0 + k * 8 + t];
            qa[k][1] = qu[row1 + k * 8 + t];
            qa[k][2] = qu[row0 + k * 8 + t + 4];
            qa[k][3] = qu[row1 + k * 8 + t + 4];
        }
    }

    // ---- prologue: first two K/V tiles via cp.async ----
    {
#pragma unroll
        for (int r = 0; r < 4; r++) {                     // K: 64 rows x 16 segs
            int idx = tid + r * 256;
            int row = idx >> 4, seg = idx & 15;
            CP_ASYNC16(sbase + OFF_K0 + row * 272 + seg * 16,
                       (const char*)kg + row * 256 + seg * 16);
        }
#pragma unroll
        for (int r = 0; r < 4; r++) {                     // V^T: 128 rows x 8 segs
            int idx = tid + r * 256;
            int row = idx >> 3, seg = idx & 7;
            CP_ASYNC16(sbase + OFF_V0 + row * 144 + seg * 16,
                       (const char*)vg + (size_t)row * NTOK * 2 + seg * 16);
        }
        CP_COMMIT();
#pragma unroll
        for (int r = 0; r < 4; r++) {
            int idx = tid + r * 256;
            int row = idx >> 4, seg = idx & 15;
            CP_ASYNC16(sbase + OFF_K1 + row * 272 + seg * 16,
                       (const char*)kg + (size_t)(64 + row) * 256 + seg * 16);
        }
#pragma unroll
        for (int r = 0; r < 4; r++) {
            int idx = tid + r * 256;
            int row = idx >> 3, seg = idx & 7;
            CP_ASYNC16(sbase + OFF_V1 + row * 144 + seg * 16,
                       (const char*)vg + (size_t)row * NTOK * 2 + 128 + seg * 16);
        }
        CP_COMMIT();
    }

    float oacc[16][4];
#pragma unroll
    for (int v = 0; v < 16; v++)
#pragma unroll
        for (int i = 0; i < 4; i++) oacc[v][i] = 0.f;
    float l0 = 0.f, l1 = 0.f;

    for (int tl = 0; tl < NTOK / 64; tl++) {
        CP_WAIT1();
        __syncthreads();

        int buf = tl & 1;
        const uint32_t* Ku = (const uint32_t*)(smem + (buf ? OFF_K1 : OFF_K0));
        const uint32_t* Vu = (const uint32_t*)(smem + (buf ? OFF_V1 : OFF_V0));

        // ---- per 8-key block: S, exp, pack (keeps register peak low) ----
        uint32_t epk[8][2];
#pragma unroll
        for (int n = 0; n < 8; n++) {
            float sacc[4] = {0.f, 0.f, 0.f, 0.f};
            int krow = (n * 8 + gr) * KROW_U32;
#pragma unroll
            for (int k = 0; k < 8; k++) {
                uint32_t b0 = Ku[krow + k * 8 + t];
                uint32_t b1 = Ku[krow + k * 8 + t + 4];
                mma_bf16(sacc, qa[k][0], qa[k][1], qa[k][2], qa[k][3], b0, b1);
            }
            float e0 = __expf(sacc[0]);
            float e1 = __expf(sacc[1]);
            float e2 = __expf(sacc[2]);
            float e3 = __expf(sacc[3]);
            l0 += e0 + e1;
            l1 += e2 + e3;
            epk[n][0] = pack_bf16x2(e0, e1);   // row gr   : keys n*8+2t, +1
            epk[n][1] = pack_bf16x2(e2, e3);   // row gr+8
        }

        // ---- O += P V : A fragments directly from epk (no shuffles) ----
#pragma unroll
        for (int u = 0; u < 4; u++) {
            uint32_t a0 = epk[2 * u][0];
            uint32_t a1 = epk[2 * u][1];
            uint32_t a2 = epk[2 * u + 1][0];
            uint32_t a3 = epk[2 * u + 1][1];
#pragma unroll
            for (int v = 0; v < 16; v++) {
                int vrow = (v * 8 + gr) * VROW_U32;
                uint32_t b0 = Vu[vrow + u * 8 + t];
                uint32_t b1 = Vu[vrow + u * 8 + t + 4];
                mma_bf16(oacc[v], a0, a1, a2, a3, b0, b1);
            }
        }

        __syncthreads();
        if (tl + 2 < NTOK / 64) {
            const char* kn = (const char*)kg + (size_t)(tl + 2) * 64 * 256;
            const char* vn = (const char*)vg + (size_t)(tl + 2) * 128;
            uint32_t koff = sbase + (buf ? OFF_K1 : OFF_K0);
            uint32_t voff = sbase + (buf ? OFF_V1 : OFF_V0);
#pragma unroll
            for (int r = 0; r < 4; r++) {
                int idx = tid + r * 256;
                int row = idx >> 4, seg = idx & 15;
                CP_ASYNC16(koff + row * 272 + seg * 16, kn + row * 256 + seg * 16);
            }
#pragma unroll
            for (int r = 0; r < 4; r++) {
                int idx = tid + r * 256;
                int row = idx >> 3, seg = idx & 7;
                CP_ASYNC16(voff + row * 144 + seg * 16, vn + (size_t)row * NTOK * 2 + seg * 16);
            }
        }
        CP_COMMIT();
    }

    // ---- finalize: reduce row sums over lane quads, normalize, store ----
    l0 += __shfl_xor_sync(0xffffffffu, l0, 1);
    l0 += __shfl_xor_sync(0xffffffffu, l0, 2);
    l1 += __shfl_xor_sync(0xffffffffu, l1, 1);
    l1 += __shfl_xor_sync(0xffffffffu, l1, 2);
    float inv0 = 1.f / l0, inv1 = 1.f / l1;

    size_t row0 = (size_t)b * NTOK + n0 + r0 + gr;
    size_t row1 = row0 + 8;
#pragma unroll
    for (int v = 0; v < 16; v++) {
        float2 w0 = {oacc[v][0] * inv0, oacc[v][1] * inv0};
        float2 w1 = {oacc[v][2] * inv1, oacc[v][3] * inv1};
        *(float2*)&g_ao[row0 * CH + v * 8 + 2 * t] = w0;
        *(float2*)&g_ao[row1 * CH + v * 8 + 2 * t] = w1;
    }
}

// ======================= K4: output projection + residual =======================
__global__ __launch_bounds__(256) void out_kernel(const float* __restrict__ x,
                                                  const float* __restrict__ wo,
                                                  const float* __restrict__ bo,
                                                  const float* __restrict__ gamma,
                                                  float* __restrict__ out) {
    int b = blockIdx.y, n0 = blockIdx.x * 64;
    __shared__ float ws[32 * 132];
    __shared__ float as_[32 * 68];
    int tid = threadIdx.x, tr = tid >> 4, tc = tid & 15;

    float acc[8][4];
#pragma unroll
    for (int oo = 0; oo < 8; oo++)
#pragma unroll
        for (int nn = 0; nn < 4; nn++) acc[oo][nn] = 0.f;

    const float* aob = g_ao + ((size_t)b * NTOK + n0) * CH;

    for (int c0 = 0; c0 < 128; c0 += 32) {
        __syncthreads();
#pragma unroll
        for (int r = 0; r < 16; r++) {
            int idx = tid + r * 256;
            int o = idx >> 5, cc = idx & 31;
            ws[cc * 132 + o] = wo[o * 128 + c0 + cc];
        }
#pragma unroll
        for (int r = 0; r < 8; r++) {
            int idx = tid + r * 256;
            int t = idx >> 5, cc = idx & 31;
            as_[cc * 68 + t] = aob[(size_t)t * CH + c0 + cc];
        }
        __syncthreads();
#pragma unroll 8
        for (int cc = 0; cc < 32; cc++) {
            float4 a4 = *(float4*)&as_[cc * 68 + tc * 4];
            float4 w0 = *(float4*)&ws[cc * 132 + tr * 8];
            float4 w1 = *(float4*)&ws[cc * 132 + tr * 8 + 4];
            float an[4] = {a4.x, a4.y, a4.z, a4.w};
            float w8[8] = {w0.x, w0.y, w0.z, w0.w, w1.x, w1.y, w1.z, w1.w};
#pragma unroll
            for (int oo = 0; oo < 8; oo++)
#pragma unroll
                for (int nn = 0; nn < 4; nn++) acc[oo][nn] += w8[oo] * an[nn];
        }
    }

    float gma = gamma[0];
#pragma unroll
    for (int oo = 0; oo < 8; oo++) {
        int o = tr * 8 + oo;
        float bv = bo[o];
        size_t idx = ((size_t)(b * CH + o)) * NTOK + n0 + tc * 4;
        float4 xr = *(const float4*)&x[idx];
        float4 o4;
        o4.x = xr.x + gma * (acc[oo][0] + bv);
        o4.y = xr.y + gma * (acc[oo][1] + bv);
        o4.z = xr.z + gma * (acc[oo][2] + bv);
        o4.w = xr.w + gma * (acc[oo][3] + bv);
        *(float4*)&out[idx] = o4;
    }
}

// ======================= launch =======================
extern "C" void kernel_launch(void* const* d_in, const int* in_sizes, int n_in,
                              void* d_out, int out_size) {
    const float* x  = (const float*)d_in[0];
    const float* gw = (const float*)d_in[1];
    const float* gb = (const float*)d_in[2];
    const float* wq = (const float*)d_in[3];
    const float* bq = (const float*)d_in[4];
    const float* wk = (const float*)d_in[5];
    const float* bk = (const float*)d_in[6];
    const float* wv = (const float*)d_in[7];
    const float* bv = (const float*)d_in[8];
    const float* wo = (const float*)d_in[9];
    const float* bo = (const float*)d_in[10];
    const float* gamma = (const float*)d_in[11];
    float* out = (float*)d_out;

    static bool attr_set = false;
    if (!attr_set) {
        cudaFuncSetAttribute(attn_mma_kernel, cudaFuncAttributeMaxDynamicSharedMemorySize, ATTN_SMEM);
        attr_set = true;
    }

    gn_kernel<<<BATCH * NGRP, 256>>>(x, gw, gb);
    qkv_kernel<<<dim3(NTOK / 64, BATCH, 3), 256>>>(wq, bq, wk, bk, wv, bv);
    attn_mma_kernel<<<dim3(NTOK / 128, BATCH), 256, ATTN_SMEM>>>();
    out_kernel<<<dim3(NTOK / 64, BATCH), 256>>>(x, wo, bo, gamma, out);
}

// round 6
// speedup vs baseline: 10.2584x; 1.3301x over previous
#include <cuda_runtime.h>
#include <cuda_bf16.h>
#include <math.h>
#include <stdint.h>

#define BATCH 8
#define CH 128
#define NTOK 4096
#define NGRP 32
#define CPG 4
#define GN_EPS 1e-5f
#define QK_SCALE 0.08838834764831845f  // 1/sqrt(128)

// ---------------- scratch (device globals; no allocations) ----------------
__device__ float2 g_stats[BATCH * NGRP];             // (mean, rstd) per (b,g)
__device__ __nv_bfloat16 g_q[BATCH * NTOK * CH];     // (b,n,c) token-major, prescaled
__device__ __nv_bfloat16 g_k[BATCH * NTOK * CH];     // (b,n,c) token-major
__device__ __nv_bfloat16 g_v[BATCH * CH * NTOK];     // (b,c,n) channel-major (V^T tiles)
__device__ __nv_bfloat16 g_ao[BATCH * NTOK * CH];    // attention output, token-major bf16

// ======================= helpers =======================
__device__ __forceinline__ uint32_t smem_u32(const void* p) {
    uint32_t a;
    asm("{ .reg .u64 t; cvta.to.shared.u64 t, %1; cvt.u32.u64 %0, t; }" : "=r"(a) : "l"(p));
    return a;
}
__device__ __forceinline__ uint32_t pack_bf16x2(float lo, float hi) {
    uint32_t r;
    asm("cvt.rn.bf16x2.f32 %0, %1, %2;" : "=r"(r) : "f"(hi), "f"(lo));
    return r;
}
// D += A*B, m16n8k16, bf16 in / fp32 accum. A row-major m16xk16, B col-major k16xn8.
__device__ __forceinline__ void mma_bf16(float* d, uint32_t a0, uint32_t a1, uint32_t a2, uint32_t a3,
                                         uint32_t b0, uint32_t b1) {
    asm volatile(
        "mma.sync.aligned.m16n8k16.row.col.f32.bf16.bf16.f32 "
        "{%0,%1,%2,%3}, {%4,%5,%6,%7}, {%8,%9}, {%0,%1,%2,%3};"
        : "+f"(d[0]), "+f"(d[1]), "+f"(d[2]), "+f"(d[3])
        : "r"(a0), "r"(a1), "r"(a2), "r"(a3), "r"(b0), "r"(b1));
}
#define LDSM_X4(r0, r1, r2, r3, addr) \
    asm volatile("ldmatrix.sync.aligned.m8n8.x4.shared.b16 {%0,%1,%2,%3}, [%4];" \
                 : "=r"(r0), "=r"(r1), "=r"(r2), "=r"(r3) : "r"(addr))
#define CP_ASYNC16(dst_u32, src_ptr) \
    asm volatile("cp.async.cg.shared.global [%0], [%1], 16;" :: "r"(dst_u32), "l"(src_ptr))
#define CP_COMMIT()  asm volatile("cp.async.commit_group;" ::: "memory")
#define CP_WAIT1()   asm volatile("cp.async.wait_group 1;" ::: "memory")

// ======================= K1: GroupNorm statistics =======================
__global__ __launch_bounds__(256) void gn_stats_kernel(const float* __restrict__ x) {
    int bg = blockIdx.x;
    size_t base = (size_t)bg * CPG * NTOK;   // bg = b*32+g, groups contiguous
    const float4* xv = (const float4*)(x + base);
    int tid = threadIdx.x;

    float s = 0.f, ss = 0.f;
#pragma unroll
    for (int r = 0; r < 16; r++) {
        float4 v = xv[tid + r * 256];
        s  += v.x + v.y + v.z + v.w;
        ss += v.x * v.x + v.y * v.y + v.z * v.z + v.w * v.w;
    }
    __shared__ float rs[8], rss[8];
#pragma unroll
    for (int o = 16; o; o >>= 1) {
        s  += __shfl_xor_sync(0xffffffffu, s, o);
        ss += __shfl_xor_sync(0xffffffffu, ss, o);
    }
    if ((tid & 31) == 0) { rs[tid >> 5] = s; rss[tid >> 5] = ss; }
    __syncthreads();
    if (tid == 0) {
        float ts = 0.f, tss = 0.f;
#pragma unroll
        for (int i = 0; i < 8; i++) { ts += rs[i]; tss += rss[i]; }
        const float invN = 1.f / (CPG * NTOK);
        float mean = ts * invN;
        float var  = tss * invN - mean * mean;
        g_stats[bg] = make_float2(mean, rsqrtf(var + GN_EPS));
    }
}

// ======================= K2: fused GN-apply + QKV (bf16 mma) =======================
// grid (16 token-tiles of 256, 8 batches). smem: xs[256][136bf16], ws[128][136bf16], stg.
#define FQ_XS 0
#define FQ_WS 69632
#define FQ_STG 104448
#define FQ_SMEM 174080

__global__ __launch_bounds__(256, 1) void fused_qkv_kernel(
        const float* __restrict__ x,
        const float* __restrict__ gw, const float* __restrict__ gb,
        const float* __restrict__ wq, const float* __restrict__ bq,
        const float* __restrict__ wk, const float* __restrict__ bk,
        const float* __restrict__ wv, const float* __restrict__ bv) {
    extern __shared__ char smem[];
    uint32_t sbase = smem_u32(smem);
    __nv_bfloat16* xs_h = (__nv_bfloat16*)(smem + FQ_XS);
    uint32_t* ws_u = (uint32_t*)(smem + FQ_WS);
    int tid = threadIdx.x, w = tid >> 5, lid = tid & 31;
    int gr = lid >> 2, t = lid & 3;
    int b = blockIdx.y, n0 = blockIdx.x * 256;
    int o0 = w * 16;

    // ---- load x tile, normalize, bf16 into xs [tok][ch] (hw stride 136) ----
#pragma unroll
    for (int r = 0; r < 32; r++) {
        int idx = tid + r * 256;
        int c = idx >> 6, seg = idx & 63;
        float4 v = *(const float4*)&x[((size_t)(b * CH + c)) * NTOK + n0 + seg * 4];
        float2 st = g_stats[b * NGRP + (c >> 2)];
        float a = gw[c] * st.y;
        float bb = gb[c] - st.x * a;
        int tok = seg * 4;
        xs_h[(tok + 0) * 136 + c] = __float2bfloat16(v.x * a + bb);
        xs_h[(tok + 1) * 136 + c] = __float2bfloat16(v.y * a + bb);
        xs_h[(tok + 2) * 136 + c] = __float2bfloat16(v.z * a + bb);
        xs_h[(tok + 3) * 136 + c] = __float2bfloat16(v.w * a + bb);
    }
    __syncthreads();

    for (int p = 0; p < 3; p++) {
        const float* W    = (p == 0) ? wq : (p == 1) ? wk : wv;
        const float* bias = (p == 0) ? bq : (p == 1) ? bk : bv;
        float postscale   = (p == 0) ? QK_SCALE : 1.0f;

        // ---- W -> bf16 smem [o][ch] (stride 68 u32) ----
#pragma unroll
        for (int r = 0; r < 16; r++) {
            int idx = tid + r * 256;
            int o = idx >> 5, seg = idx & 31;
            float4 w4 = *(const float4*)&W[o * 128 + seg * 4];
            uint2 pk;
            pk.x = pack_bf16x2(w4.x, w4.y);
            pk.y = pack_bf16x2(w4.z, w4.w);
            *(uint2*)&ws_u[o * 68 + seg * 2] = pk;
        }
        __syncthreads();

        // ---- A fragments (W m-tile for this warp) ----
        uint32_t af[8][4];
        {
            uint32_t abase = sbase + FQ_WS + (uint32_t)(o0 + (lid & 15)) * 272 + (uint32_t)(lid >> 4) * 16;
#pragma unroll
            for (int c = 0; c < 8; c++)
                LDSM_X4(af[c][0], af[c][1], af[c][2], af[c][3], abase + c * 32);
        }
        float bias0 = bias[o0 + gr];
        float bias1 = bias[o0 + 8 + gr];

        // ---- GEMM over 32 token n-blocks ----
        uint32_t bbase = sbase + FQ_XS + (uint32_t)(lid & 7) * 272 + (uint32_t)(lid >> 3) * 16;
#pragma unroll 4
        for (int nb = 0; nb < 32; nb++) {
            float d[4] = {0.f, 0.f, 0.f, 0.f};
#pragma unroll
            for (int cp = 0; cp < 4; cp++) {
                uint32_t b0, b1, b2, b3;
                LDSM_X4(b0, b1, b2, b3, bbase + (uint32_t)nb * 2176 + cp * 64);
                mma_bf16(d, af[2 * cp][0], af[2 * cp][1], af[2 * cp][2], af[2 * cp][3], b0, b1);
                mma_bf16(d, af[2 * cp + 1][0], af[2 * cp + 1][1], af[2 * cp + 1][2], af[2 * cp + 1][3], b2, b3);
            }
            float v0 = (d[0] + bias0) * postscale;
            float v1 = (d[1] + bias0) * postscale;
            float v2 = (d[2] + bias1) * postscale;
            float v3 = (d[3] + bias1) * postscale;
            if (p == 2) {
                // stage [ch][tok] u32 (stride 132 u32), tokens adjacent
                uint32_t* stg = (uint32_t*)(smem + FQ_STG);
                stg[(o0 + gr) * 132 + nb * 4 + t] = pack_bf16x2(v0, v1);
                stg[(o0 + 8 + gr) * 132 + nb * 4 + t] = pack_bf16x2(v2, v3);
            } else {
                // stage [tok][ch] halfwords (stride 136 hw)
                __nv_bfloat16* stg = (__nv_bfloat16*)(smem + FQ_STG);
                int tok = nb * 8 + 2 * t;
                stg[tok * 136 + o0 + gr] = __float2bfloat16(v0);
                stg[(tok + 1) * 136 + o0 + gr] = __float2bfloat16(v1);
                stg[tok * 136 + o0 + 8 + gr] = __float2bfloat16(v2);
                stg[(tok + 1) * 136 + o0 + 8 + gr] = __float2bfloat16(v3);
            }
        }
        __syncthreads();

        // ---- coalesced copy staging -> global ----
        if (p == 2) {
            // 128 ch rows x 512 B (256 tok bf16) = 32 segs/row, stride 528 B
#pragma unroll
            for (int r = 0; r < 16; r++) {
                int idx = tid + r * 256;
                int c = idx >> 5, seg = idx & 31;
                uint4 v = *(uint4*)(smem + FQ_STG + c * 528 + seg * 16);
                *(uint4*)((char*)g_v + (((size_t)(b * CH + c)) * NTOK + n0) * 2 + seg * 16) = v;
            }
        } else {
            // 256 tok rows x 256 B (128 ch bf16) = 16 segs/row, stride 272 B
            __nv_bfloat16* dst = (p == 0) ? g_q : g_k;
#pragma unroll
            for (int r = 0; r < 16; r++) {
                int idx = tid + r * 256;
                int tok = idx >> 4, seg = idx & 15;
                uint4 v = *(uint4*)(smem + FQ_STG + tok * 272 + seg * 16);
                *(uint4*)((char*)dst + ((size_t)b * NTOK + n0 + tok) * 256 + seg * 16) = v;
            }
        }
        __syncthreads();
    }
}

// ======================= K3: mma.sync bf16 flash attention (ldmatrix) =======================
#define KTILE_B (64 * 272)                    // K tile [64 key][136 bf16]
#define VTILE_B (128 * 144)                   // V^T tile [128 ch][72 bf16]
#define OFF_K0 0
#define OFF_K1 KTILE_B
#define OFF_V0 (2 * KTILE_B)
#define OFF_V1 (2 * KTILE_B + VTILE_B)
#define ATTN_SMEM (2 * KTILE_B + 2 * VTILE_B) // 71680 B

__global__ __launch_bounds__(256, 2) void attn_mma_kernel() {
    extern __shared__ char smem[];
    uint32_t sbase = smem_u32(smem);
    int tid = threadIdx.x;
    int w = tid >> 5, lid = tid & 31;
    int gr = lid >> 2, t = lid & 3;
    int r0 = w * 16;
    int b = blockIdx.y, n0 = blockIdx.x * 128;

    const __nv_bfloat16* kg = g_k + (size_t)b * NTOK * CH;   // token-major
    const __nv_bfloat16* vg = g_v + (size_t)b * CH * NTOK;   // channel-major

    // ---- Q fragments: loop-invariant, in registers ----
    uint32_t qa[8][4];
    {
        const uint32_t* qu = (const uint32_t*)(g_q + ((size_t)b * NTOK + n0) * CH);
        int row0 = (r0 + gr) * 64, row1 = (r0 + gr + 8) * 64;
#pragma unroll
        for (int k = 0; k < 8; k++) {
            qa[k][0] = qu[row0 + k * 8 + t];
            qa[k][1] = qu[row1 + k * 8 + t];
            qa[k][2] = qu[row0 + k * 8 + t + 4];
            qa[k][3] = qu[row1 + k * 8 + t + 4];
        }
    }

    // ---- prologue: first two K/V tiles ----
    {
#pragma unroll
        for (int r = 0; r < 4; r++) {
            int idx = tid + r * 256;
            int row = idx >> 4, seg = idx & 15;
            CP_ASYNC16(sbase + OFF_K0 + row * 272 + seg * 16, (const char*)kg + row * 256 + seg * 16);
        }
#pragma unroll
        for (int r = 0; r < 4; r++) {
            int idx = tid + r * 256;
            int row = idx >> 3, seg = idx & 7;
            CP_ASYNC16(sbase + OFF_V0 + row * 144 + seg * 16, (const char*)vg + (size_t)row * NTOK * 2 + seg * 16);
        }
        CP_COMMIT();
#pragma unroll
        for (int r = 0; r < 4; r++) {
            int idx = tid + r * 256;
            int row = idx >> 4, seg = idx & 15;
            CP_ASYNC16(sbase + OFF_K1 + row * 272 + seg * 16,
                       (const char*)kg + (size_t)(64 + row) * 256 + seg * 16);
        }
#pragma unroll
        for (int r = 0; r < 4; r++) {
            int idx = tid + r * 256;
            int row = idx >> 3, seg = idx & 7;
            CP_ASYNC16(sbase + OFF_V1 + row * 144 + seg * 16,
                       (const char*)vg + (size_t)row * NTOK * 2 + 128 + seg * 16);
        }
        CP_COMMIT();
    }

    float oacc[16][4];
#pragma unroll
    for (int v = 0; v < 16; v++)
#pragma unroll
        for (int i = 0; i < 4; i++) oacc[v][i] = 0.f;
    float l0 = 0.f, l1 = 0.f;

    uint32_t klane = (uint32_t)(lid & 7) * 272 + (uint32_t)(lid >> 3) * 16;
    uint32_t vlane = (uint32_t)(lid & 7) * 144 + (uint32_t)(lid >> 3) * 16;

    for (int tl = 0; tl < NTOK / 64; tl++) {
        CP_WAIT1();
        __syncthreads();

        int buf = tl & 1;
        uint32_t kb = sbase + (buf ? OFF_K1 : OFF_K0) + klane;
        uint32_t vb = sbase + (buf ? OFF_V1 : OFF_V0) + vlane;

        // ---- S = Q K^T, exp, pack ----
        uint32_t epk[8][2];
#pragma unroll
        for (int n = 0; n < 8; n++) {
            float sacc[4] = {0.f, 0.f, 0.f, 0.f};
            uint32_t krow = kb + (uint32_t)n * 2176;
#pragma unroll
            for (int cp = 0; cp < 4; cp++) {
                uint32_t b0, b1, b2, b3;
                LDSM_X4(b0, b1, b2, b3, krow + cp * 64);
                mma_bf16(sacc, qa[2 * cp][0], qa[2 * cp][1], qa[2 * cp][2], qa[2 * cp][3], b0, b1);
                mma_bf16(sacc, qa[2 * cp + 1][0], qa[2 * cp + 1][1], qa[2 * cp + 1][2], qa[2 * cp + 1][3], b2, b3);
            }
            float e0 = __expf(sacc[0]);
            float e1 = __expf(sacc[1]);
            float e2 = __expf(sacc[2]);
            float e3 = __expf(sacc[3]);
            l0 += e0 + e1;
            l1 += e2 + e3;
            epk[n][0] = pack_bf16x2(e0, e1);
            epk[n][1] = pack_bf16x2(e2, e3);
        }

        // ---- O += P V ----
#pragma unroll
        for (int up = 0; up < 2; up++) {
            uint32_t a00 = epk[4 * up][0],     a01 = epk[4 * up][1];
            uint32_t a10 = epk[4 * up + 1][0], a11 = epk[4 * up + 1][1];
            uint32_t a20 = epk[4 * up + 2][0], a21 = epk[4 * up + 2][1];
            uint32_t a30 = epk[4 * up + 3][0], a31 = epk[4 * up + 3][1];
#pragma unroll
            for (int v = 0; v < 16; v++) {
                uint32_t b0, b1, b2, b3;
                LDSM_X4(b0, b1, b2, b3, vb + (uint32_t)v * 1152 + up * 64);
                mma_bf16(oacc[v], a00, a01, a10, a11, b0, b1);
                mma_bf16(oacc[v], a20, a21, a30, a31, b2, b3);
            }
        }

        __syncthreads();
        if (tl + 2 < NTOK / 64) {
            const char* kn = (const char*)kg + (size_t)(tl + 2) * 64 * 256;
            const char* vn = (const char*)vg + (size_t)(tl + 2) * 128;
            uint32_t koff = sbase + (buf ? OFF_K1 : OFF_K0);
            uint32_t voff = sbase + (buf ? OFF_V1 : OFF_V0);
#pragma unroll
            for (int r = 0; r < 4; r++) {
                int idx = tid + r * 256;
                int row = idx >> 4, seg = idx & 15;
                CP_ASYNC16(koff + row * 272 + seg * 16, kn + row * 256 + seg * 16);
            }
#pragma unroll
            for (int r = 0; r < 4; r++) {
                int idx = tid + r * 256;
                int row = idx >> 3, seg = idx & 7;
                CP_ASYNC16(voff + row * 144 + seg * 16, vn + (size_t)row * NTOK * 2 + seg * 16);
            }
        }
        CP_COMMIT();
    }

    // ---- finalize: reduce row sums, normalize, bf16 store ----
    l0 += __shfl_xor_sync(0xffffffffu, l0, 1);
    l0 += __shfl_xor_sync(0xffffffffu, l0, 2);
    l1 += __shfl_xor_sync(0xffffffffu, l1, 1);
    l1 += __shfl_xor_sync(0xffffffffu, l1, 2);
    float inv0 = 1.f / l0, inv1 = 1.f / l1;

    size_t row0 = (size_t)b * NTOK + n0 + r0 + gr;
    size_t row1 = row0 + 8;
    uint32_t* aou = (uint32_t*)g_ao;
#pragma unroll
    for (int v = 0; v < 16; v++) {
        aou[row0 * 64 + v * 4 + t] = pack_bf16x2(oacc[v][0] * inv0, oacc[v][1] * inv0);
        aou[row1 * 64 + v * 4 + t] = pack_bf16x2(oacc[v][2] * inv1, oacc[v][3] * inv1);
    }
}

// ======================= K4: output projection + residual =======================
__global__ __launch_bounds__(256) void out_kernel(const float* __restrict__ x,
                                                  const float* __restrict__ wo,
                                                  const float* __restrict__ bo,
                                                  const float* __restrict__ gamma,
                                                  float* __restrict__ out) {
    int b = blockIdx.y, n0 = blockIdx.x * 64;
    __shared__ float ws[32 * 132];
    __shared__ float as_[32 * 68];
    int tid = threadIdx.x, tr = tid >> 4, tc = tid & 15;

    float acc[8][4];
#pragma unroll
    for (int oo = 0; oo < 8; oo++)
#pragma unroll
        for (int nn = 0; nn < 4; nn++) acc[oo][nn] = 0.f;

    const __nv_bfloat16* aob = g_ao + ((size_t)b * NTOK + n0) * CH;

    for (int c0 = 0; c0 < 128; c0 += 32) {
        __syncthreads();
#pragma unroll
        for (int r = 0; r < 16; r++) {
            int idx = tid + r * 256;
            int o = idx >> 5, cc = idx & 31;
            ws[cc * 132 + o] = wo[o * 128 + c0 + cc];
        }
#pragma unroll
        for (int r = 0; r < 8; r++) {
            int idx = tid + r * 256;
            int t = idx >> 5, cc = idx & 31;
            as_[cc * 68 + t] = __bfloat162float(aob[(size_t)t * CH + c0 + cc]);
        }
        __syncthreads();
#pragma unroll 8
        for (int cc = 0; cc < 32; cc++) {
            float4 a4 = *(float4*)&as_[cc * 68 + tc * 4];
            float4 w0 = *(float4*)&ws[cc * 132 + tr * 8];
            float4 w1 = *(float4*)&ws[cc * 132 + tr * 8 + 4];
            float an[4] = {a4.x, a4.y, a4.z, a4.w};
            float w8[8] = {w0.x, w0.y, w0.z, w0.w, w1.x, w1.y, w1.z, w1.w};
#pragma unroll
            for (int oo = 0; oo < 8; oo++)
#pragma unroll
                for (int nn = 0; nn < 4; nn++) acc[oo][nn] += w8[oo] * an[nn];
        }
    }

    float gma = gamma[0];
#pragma unroll
    for (int oo = 0; oo < 8; oo++) {
        int o = tr * 8 + oo;
        float bv = bo[o];
        size_t idx = ((size_t)(b * CH + o)) * NTOK + n0 + tc * 4;
        float4 xr = *(const float4*)&x[idx];
        float4 o4;
        o4.x = xr.x + gma * (acc[oo][0] + bv);
        o4.y = xr.y + gma * (acc[oo][1] + bv);
        o4.z = xr.z + gma * (acc[oo][2] + bv);
        o4.w = xr.w + gma * (acc[oo][3] + bv);
        *(float4*)&out[idx] = o4;
    }
}

// ======================= launch =======================
extern "C" void kernel_launch(void* const* d_in, const int* in_sizes, int n_in,
                              void* d_out, int out_size) {
    const float* x  = (const float*)d_in[0];
    const float* gw = (const float*)d_in[1];
    const float* gb = (const float*)d_in[2];
    const float* wq = (const float*)d_in[3];
    const float* bq = (const float*)d_in[4];
    const float* wk = (const float*)d_in[5];
    const float* bk = (const float*)d_in[6];
    const float* wv = (const float*)d_in[7];
    const float* bv = (const float*)d_in[8];
    const float* wo = (const float*)d_in[9];
    const float* bo = (const float*)d_in[10];
    const float* gamma = (const float*)d_in[11];
    float* out = (float*)d_out;

    static bool attr_set = false;
    if (!attr_set) {
        cudaFuncSetAttribute(attn_mma_kernel, cudaFuncAttributeMaxDynamicSharedMemorySize, ATTN_SMEM);
        cudaFuncSetAttribute(fused_qkv_kernel, cudaFuncAttributeMaxDynamicSharedMemorySize, FQ_SMEM);
        attr_set = true;
    }

    gn_stats_kernel<<<BATCH * NGRP, 256>>>(x);
    fused_qkv_kernel<<<dim3(NTOK / 256, BATCH), 256, FQ_SMEM>>>(x, gw, gb, wq, bq, wk, bk, wv, bv);
    attn_mma_kernel<<<dim3(NTOK / 128, BATCH), 256, ATTN_SMEM>>>();
    out_kernel<<<dim3(NTOK / 64, BATCH), 256>>>(x, wo, bo, gamma, out);
}

// round 7
// speedup vs baseline: 11.1150x; 1.0835x over previous
#include <cuda_runtime.h>
#include <cuda_bf16.h>
#include <math.h>
#include <stdint.h>

#define BATCH 8
#define CH 128
#define NTOK 4096
#define NGRP 32
#define CPG 4
#define GN_EPS 1e-5f
#define QK_SCALE 0.08838834764831845f  // 1/sqrt(128)

// ---------------- scratch (device globals; no allocations) ----------------
__device__ float2 g_stats[BATCH * NGRP];             // (mean, rstd) per (b,g)
__device__ __nv_bfloat16 g_q[BATCH * NTOK * CH];     // (b,n,c) token-major, prescaled
__device__ __nv_bfloat16 g_k[BATCH * NTOK * CH];     // (b,n,c) token-major
__device__ __nv_bfloat16 g_v[BATCH * CH * NTOK];     // (b,c,n) channel-major (V^T tiles)

// ======================= helpers =======================
__device__ __forceinline__ uint32_t smem_u32(const void* p) {
    uint32_t a;
    asm("{ .reg .u64 t; cvta.to.shared.u64 t, %1; cvt.u32.u64 %0, t; }" : "=r"(a) : "l"(p));
    return a;
}
__device__ __forceinline__ uint32_t pack_bf16x2(float lo, float hi) {
    uint32_t r;
    asm("cvt.rn.bf16x2.f32 %0, %1, %2;" : "=r"(r) : "f"(hi), "f"(lo));
    return r;
}
// D += A*B, m16n8k16, bf16 in / fp32 accum. A row-major m16xk16, B col-major k16xn8.
__device__ __forceinline__ void mma_bf16(float* d, uint32_t a0, uint32_t a1, uint32_t a2, uint32_t a3,
                                         uint32_t b0, uint32_t b1) {
    asm volatile(
        "mma.sync.aligned.m16n8k16.row.col.f32.bf16.bf16.f32 "
        "{%0,%1,%2,%3}, {%4,%5,%6,%7}, {%8,%9}, {%0,%1,%2,%3};"
        : "+f"(d[0]), "+f"(d[1]), "+f"(d[2]), "+f"(d[3])
        : "r"(a0), "r"(a1), "r"(a2), "r"(a3), "r"(b0), "r"(b1));
}
#define LDSM_X4(r0, r1, r2, r3, addr) \
    asm volatile("ldmatrix.sync.aligned.m8n8.x4.shared.b16 {%0,%1,%2,%3}, [%4];" \
                 : "=r"(r0), "=r"(r1), "=r"(r2), "=r"(r3) : "r"(addr))
#define CP_ASYNC16(dst_u32, src_ptr) \
    asm volatile("cp.async.cg.shared.global [%0], [%1], 16;" :: "r"(dst_u32), "l"(src_ptr))
#define CP_COMMIT()  asm volatile("cp.async.commit_group;" ::: "memory")
#define CP_WAIT1()   asm volatile("cp.async.wait_group 1;" ::: "memory")

// ======================= K1: GroupNorm statistics =======================
__global__ __launch_bounds__(256) void gn_stats_kernel(const float* __restrict__ x) {
    int bg = blockIdx.x;
    size_t base = (size_t)bg * CPG * NTOK;
    const float4* xv = (const float4*)(x + base);
    int tid = threadIdx.x;

    float s = 0.f, ss = 0.f;
#pragma unroll
    for (int r = 0; r < 16; r++) {
        float4 v = xv[tid + r * 256];
        s  += v.x + v.y + v.z + v.w;
        ss += v.x * v.x + v.y * v.y + v.z * v.z + v.w * v.w;
    }
    __shared__ float rs[8], rss[8];
#pragma unroll
    for (int o = 16; o; o >>= 1) {
        s  += __shfl_xor_sync(0xffffffffu, s, o);
        ss += __shfl_xor_sync(0xffffffffu, ss, o);
    }
    if ((tid & 31) == 0) { rs[tid >> 5] = s; rss[tid >> 5] = ss; }
    __syncthreads();
    if (tid == 0) {
        float ts = 0.f, tss = 0.f;
#pragma unroll
        for (int i = 0; i < 8; i++) { ts += rs[i]; tss += rss[i]; }
        const float invN = 1.f / (CPG * NTOK);
        float mean = ts * invN;
        float var  = tss * invN - mean * mean;
        g_stats[bg] = make_float2(mean, rsqrtf(var + GN_EPS));
    }
}

// ======================= K2: fused GN-apply + QKV (bf16 mma) =======================
#define FQ_XS 0
#define FQ_WS 69632
#define FQ_STG 104448
#define FQ_SMEM 174080

__global__ __launch_bounds__(256, 1) void fused_qkv_kernel(
        const float* __restrict__ x,
        const float* __restrict__ gw, const float* __restrict__ gb,
        const float* __restrict__ wq, const float* __restrict__ bq,
        const float* __restrict__ wk, const float* __restrict__ bk,
        const float* __restrict__ wv, const float* __restrict__ bv) {
    extern __shared__ char smem[];
    uint32_t sbase = smem_u32(smem);
    __nv_bfloat16* xs_h = (__nv_bfloat16*)(smem + FQ_XS);
    uint32_t* ws_u = (uint32_t*)(smem + FQ_WS);
    int tid = threadIdx.x, w = tid >> 5, lid = tid & 31;
    int gr = lid >> 2, t = lid & 3;
    int b = blockIdx.y, n0 = blockIdx.x * 256;
    int o0 = w * 16;

#pragma unroll
    for (int r = 0; r < 32; r++) {
        int idx = tid + r * 256;
        int c = idx >> 6, seg = idx & 63;
        float4 v = *(const float4*)&x[((size_t)(b * CH + c)) * NTOK + n0 + seg * 4];
        float2 st = g_stats[b * NGRP + (c >> 2)];
        float a = gw[c] * st.y;
        float bb = gb[c] - st.x * a;
        int tok = seg * 4;
        xs_h[(tok + 0) * 136 + c] = __float2bfloat16(v.x * a + bb);
        xs_h[(tok + 1) * 136 + c] = __float2bfloat16(v.y * a + bb);
        xs_h[(tok + 2) * 136 + c] = __float2bfloat16(v.z * a + bb);
        xs_h[(tok + 3) * 136 + c] = __float2bfloat16(v.w * a + bb);
    }
    __syncthreads();

    for (int p = 0; p < 3; p++) {
        const float* W    = (p == 0) ? wq : (p == 1) ? wk : wv;
        const float* bias = (p == 0) ? bq : (p == 1) ? bk : bv;
        float postscale   = (p == 0) ? QK_SCALE : 1.0f;

#pragma unroll
        for (int r = 0; r < 16; r++) {
            int idx = tid + r * 256;
            int o = idx >> 5, seg = idx & 31;
            float4 w4 = *(const float4*)&W[o * 128 + seg * 4];
            uint2 pk;
            pk.x = pack_bf16x2(w4.x, w4.y);
            pk.y = pack_bf16x2(w4.z, w4.w);
            *(uint2*)&ws_u[o * 68 + seg * 2] = pk;
        }
        __syncthreads();

        uint32_t af[8][4];
        {
            uint32_t abase = sbase + FQ_WS + (uint32_t)(o0 + (lid & 15)) * 272 + (uint32_t)(lid >> 4) * 16;
#pragma unroll
            for (int c = 0; c < 8; c++)
                LDSM_X4(af[c][0], af[c][1], af[c][2], af[c][3], abase + c * 32);
        }
        float bias0 = bias[o0 + gr];
        float bias1 = bias[o0 + 8 + gr];

        uint32_t bbase = sbase + FQ_XS + (uint32_t)(lid & 7) * 272 + (uint32_t)(lid >> 3) * 16;
#pragma unroll 4
        for (int nb = 0; nb < 32; nb++) {
            float d[4] = {0.f, 0.f, 0.f, 0.f};
#pragma unroll
            for (int cp = 0; cp < 4; cp++) {
                uint32_t b0, b1, b2, b3;
                LDSM_X4(b0, b1, b2, b3, bbase + (uint32_t)nb * 2176 + cp * 64);
                mma_bf16(d, af[2 * cp][0], af[2 * cp][1], af[2 * cp][2], af[2 * cp][3], b0, b1);
                mma_bf16(d, af[2 * cp + 1][0], af[2 * cp + 1][1], af[2 * cp + 1][2], af[2 * cp + 1][3], b2, b3);
            }
            float v0 = (d[0] + bias0) * postscale;
            float v1 = (d[1] + bias0) * postscale;
            float v2 = (d[2] + bias1) * postscale;
            float v3 = (d[3] + bias1) * postscale;
            if (p == 2) {
                uint32_t* stg = (uint32_t*)(smem + FQ_STG);
                stg[(o0 + gr) * 132 + nb * 4 + t] = pack_bf16x2(v0, v1);
                stg[(o0 + 8 + gr) * 132 + nb * 4 + t] = pack_bf16x2(v2, v3);
            } else {
                __nv_bfloat16* stg = (__nv_bfloat16*)(smem + FQ_STG);
                int tok = nb * 8 + 2 * t;
                stg[tok * 136 + o0 + gr] = __float2bfloat16(v0);
                stg[(tok + 1) * 136 + o0 + gr] = __float2bfloat16(v1);
                stg[tok * 136 + o0 + 8 + gr] = __float2bfloat16(v2);
                stg[(tok + 1) * 136 + o0 + 8 + gr] = __float2bfloat16(v3);
            }
        }
        __syncthreads();

        if (p == 2) {
#pragma unroll
            for (int r = 0; r < 16; r++) {
                int idx = tid + r * 256;
                int c = idx >> 5, seg = idx & 31;
                uint4 v = *(uint4*)(smem + FQ_STG + c * 528 + seg * 16);
                *(uint4*)((char*)g_v + (((size_t)(b * CH + c)) * NTOK + n0) * 2 + seg * 16) = v;
            }
        } else {
            __nv_bfloat16* dst = (p == 0) ? g_q : g_k;
#pragma unroll
            for (int r = 0; r < 16; r++) {
                int idx = tid + r * 256;
                int tok = idx >> 4, seg = idx & 15;
                uint4 v = *(uint4*)(smem + FQ_STG + tok * 272 + seg * 16);
                *(uint4*)((char*)dst + ((size_t)b * NTOK + n0 + tok) * 256 + seg * 16) = v;
            }
        }
        __syncthreads();
    }
}

// ======================= K3: flash attention + fused output projection =======================
#define KTILE_B (64 * 272)                    // K tile [64 key][136 bf16]
#define VTILE_B (128 * 144)                   // V^T tile [128 ch][72 bf16]
#define OFF_K0 0
#define OFF_K1 KTILE_B
#define OFF_V0 (2 * KTILE_B)
#define OFF_V1 (2 * KTILE_B + VTILE_B)
#define ATTN_SMEM (2 * KTILE_B + 2 * VTILE_B) // 71680 B
// epilogue reuse: Wo bf16 [128 o][136] at OFF_K0 (34816 B = K0+K1);
//                 staging bf16 [128 o][136 tok] at OFF_V0 (34816 B <= V0+V1)

__global__ __launch_bounds__(256, 2) void attn_fused_kernel(
        const float* __restrict__ x,
        const float* __restrict__ wo, const float* __restrict__ bo,
        const float* __restrict__ gamma, float* __restrict__ out) {
    extern __shared__ char smem[];
    uint32_t sbase = smem_u32(smem);
    int tid = threadIdx.x;
    int w = tid >> 5, lid = tid & 31;
    int gr = lid >> 2, t = lid & 3;
    int r0 = w * 16;
    int b = blockIdx.y, n0 = blockIdx.x * 128;

    const __nv_bfloat16* kg = g_k + (size_t)b * NTOK * CH;
    const __nv_bfloat16* vg = g_v + (size_t)b * CH * NTOK;

    // ---- Q fragments ----
    uint32_t qa[8][4];
    {
        const uint32_t* qu = (const uint32_t*)(g_q + ((size_t)b * NTOK + n0) * CH);
        int row0 = (r0 + gr) * 64, row1 = (r0 + gr + 8) * 64;
#pragma unroll
        for (int k = 0; k < 8; k++) {
            qa[k][0] = qu[row0 + k * 8 + t];
            qa[k][1] = qu[row1 + k * 8 + t];
            qa[k][2] = qu[row0 + k * 8 + t + 4];
            qa[k][3] = qu[row1 + k * 8 + t + 4];
        }
    }

    // ---- prologue: first two K/V tiles ----
    {
#pragma unroll
        for (int r = 0; r < 4; r++) {
            int idx = tid + r * 256;
            int row = idx >> 4, seg = idx & 15;
            CP_ASYNC16(sbase + OFF_K0 + row * 272 + seg * 16, (const char*)kg + row * 256 + seg * 16);
        }
#pragma unroll
        for (int r = 0; r < 4; r++) {
            int idx = tid + r * 256;
            int row = idx >> 3, seg = idx & 7;
            CP_ASYNC16(sbase + OFF_V0 + row * 144 + seg * 16, (const char*)vg + (size_t)row * NTOK * 2 + seg * 16);
        }
        CP_COMMIT();
#pragma unroll
        for (int r = 0; r < 4; r++) {
            int idx = tid + r * 256;
            int row = idx >> 4, seg = idx & 15;
            CP_ASYNC16(sbase + OFF_K1 + row * 272 + seg * 16,
                       (const char*)kg + (size_t)(64 + row) * 256 + seg * 16);
        }
#pragma unroll
        for (int r = 0; r < 4; r++) {
            int idx = tid + r * 256;
            int row = idx >> 3, seg = idx & 7;
            CP_ASYNC16(sbase + OFF_V1 + row * 144 + seg * 16,
                       (const char*)vg + (size_t)row * NTOK * 2 + 128 + seg * 16);
        }
        CP_COMMIT();
    }

    float oacc[16][4];
#pragma unroll
    for (int v = 0; v < 16; v++)
#pragma unroll
        for (int i = 0; i < 4; i++) oacc[v][i] = 0.f;
    float l0 = 0.f, l1 = 0.f;

    uint32_t klane = (uint32_t)(lid & 7) * 272 + (uint32_t)(lid >> 3) * 16;
    uint32_t vlane = (uint32_t)(lid & 7) * 144 + (uint32_t)(lid >> 3) * 16;

    for (int tl = 0; tl < NTOK / 64; tl++) {
        CP_WAIT1();
        __syncthreads();

        int buf = tl & 1;
        uint32_t kb = sbase + (buf ? OFF_K1 : OFF_K0) + klane;
        uint32_t vb = sbase + (buf ? OFF_V1 : OFF_V0) + vlane;

        uint32_t epk[8][2];
#pragma unroll
        for (int n = 0; n < 8; n++) {
            float sacc[4] = {0.f, 0.f, 0.f, 0.f};
            uint32_t krow = kb + (uint32_t)n * 2176;
#pragma unroll
            for (int cp = 0; cp < 4; cp++) {
                uint32_t b0, b1, b2, b3;
                LDSM_X4(b0, b1, b2, b3, krow + cp * 64);
                mma_bf16(sacc, qa[2 * cp][0], qa[2 * cp][1], qa[2 * cp][2], qa[2 * cp][3], b0, b1);
                mma_bf16(sacc, qa[2 * cp + 1][0], qa[2 * cp + 1][1], qa[2 * cp + 1][2], qa[2 * cp + 1][3], b2, b3);
            }
            float e0 = __expf(sacc[0]);
            float e1 = __expf(sacc[1]);
            float e2 = __expf(sacc[2]);
            float e3 = __expf(sacc[3]);
            l0 += e0 + e1;
            l1 += e2 + e3;
            epk[n][0] = pack_bf16x2(e0, e1);
            epk[n][1] = pack_bf16x2(e2, e3);
        }

#pragma unroll
        for (int up = 0; up < 2; up++) {
            uint32_t a00 = epk[4 * up][0],     a01 = epk[4 * up][1];
            uint32_t a10 = epk[4 * up + 1][0], a11 = epk[4 * up + 1][1];
            uint32_t a20 = epk[4 * up + 2][0], a21 = epk[4 * up + 2][1];
            uint32_t a30 = epk[4 * up + 3][0], a31 = epk[4 * up + 3][1];
#pragma unroll
            for (int v = 0; v < 16; v++) {
                uint32_t b0, b1, b2, b3;
                LDSM_X4(b0, b1, b2, b3, vb + (uint32_t)v * 1152 + up * 64);
                mma_bf16(oacc[v], a00, a01, a10, a11, b0, b1);
                mma_bf16(oacc[v], a20, a21, a30, a31, b2, b3);
            }
        }

        __syncthreads();
        if (tl + 2 < NTOK / 64) {
            const char* kn = (const char*)kg + (size_t)(tl + 2) * 64 * 256;
            const char* vn = (const char*)vg + (size_t)(tl + 2) * 128;
            uint32_t koff = sbase + (buf ? OFF_K1 : OFF_K0);
            uint32_t voff = sbase + (buf ? OFF_V1 : OFF_V0);
#pragma unroll
            for (int r = 0; r < 4; r++) {
                int idx = tid + r * 256;
                int row = idx >> 4, seg = idx & 15;
                CP_ASYNC16(koff + row * 272 + seg * 16, kn + row * 256 + seg * 16);
            }
#pragma unroll
            for (int r = 0; r < 4; r++) {
                int idx = tid + r * 256;
                int row = idx >> 3, seg = idx & 7;
                CP_ASYNC16(voff + row * 144 + seg * 16, vn + (size_t)row * NTOK * 2 + seg * 16);
            }
        }
        CP_COMMIT();
    }

    // ---- row sums ----
    l0 += __shfl_xor_sync(0xffffffffu, l0, 1);
    l0 += __shfl_xor_sync(0xffffffffu, l0, 2);
    l1 += __shfl_xor_sync(0xffffffffu, l1, 1);
    l1 += __shfl_xor_sync(0xffffffffu, l1, 2);
    float inv0 = 1.f / l0, inv1 = 1.f / l1;

    // ======== fused output projection epilogue ========
    // A fragments for out-proj GEMM come straight from oacc (accumulator->A-fragment identity).
    uint32_t af[8][4];
#pragma unroll
    for (int cp = 0; cp < 8; cp++) {
        af[cp][0] = pack_bf16x2(oacc[2 * cp][0] * inv0,     oacc[2 * cp][1] * inv0);
        af[cp][1] = pack_bf16x2(oacc[2 * cp][2] * inv1,     oacc[2 * cp][3] * inv1);
        af[cp][2] = pack_bf16x2(oacc[2 * cp + 1][0] * inv0, oacc[2 * cp + 1][1] * inv0);
        af[cp][3] = pack_bf16x2(oacc[2 * cp + 1][2] * inv1, oacc[2 * cp + 1][3] * inv1);
    }

    // Wo -> bf16 smem [o][c] stride 272 B (reuse K-tile region; all K reads finished pre-sync)
    {
        uint32_t* wsm = (uint32_t*)(smem + OFF_K0);
#pragma unroll
        for (int r = 0; r < 16; r++) {
            int idx = tid + r * 256;
            int o = idx >> 5, seg = idx & 31;
            float4 w4 = *(const float4*)&wo[o * 128 + seg * 4];
            wsm[o * 68 + seg * 2]     = pack_bf16x2(w4.x, w4.y);
            wsm[o * 68 + seg * 2 + 1] = pack_bf16x2(w4.z, w4.w);
        }
    }
    __syncthreads();

    // out_p[tok][o], staged bf16 [o][tok] (stride 272 B) in dead V region
    __nv_bfloat16* stg = (__nv_bfloat16*)(smem + OFF_V0);
    uint32_t wob = sbase + OFF_K0 + klane;
#pragma unroll
    for (int nb = 0; nb < 16; nb++) {
        float d[4] = {0.f, 0.f, 0.f, 0.f};
#pragma unroll
        for (int cp = 0; cp < 4; cp++) {
            uint32_t b0, b1, b2, b3;
            LDSM_X4(b0, b1, b2, b3, wob + (uint32_t)nb * 2176 + cp * 64);
            mma_bf16(d, af[2 * cp][0], af[2 * cp][1], af[2 * cp][2], af[2 * cp][3], b0, b1);
            mma_bf16(d, af[2 * cp + 1][0], af[2 * cp + 1][1], af[2 * cp + 1][2], af[2 * cp + 1][3], b2, b3);
        }
        int o = nb * 8 + 2 * t;
        stg[o * 136 + r0 + gr]           = __float2bfloat16(d[0]);
        stg[(o + 1) * 136 + r0 + gr]     = __float2bfloat16(d[1]);
        stg[o * 136 + r0 + gr + 8]       = __float2bfloat16(d[2]);
        stg[(o + 1) * 136 + r0 + gr + 8] = __float2bfloat16(d[3]);
    }
    __syncthreads();

    // residual + bias + gamma, coalesced fp32 write
    float gma = gamma[0];
#pragma unroll
    for (int r = 0; r < 8; r++) {
        int idx = tid + r * 256;
        int o = idx >> 4, seg = idx & 15;
        uint4 pv = *(uint4*)((char*)stg + o * 272 + seg * 16);   // 8 bf16 tokens
        float bv = bo[o];
        size_t gidx = ((size_t)(b * CH + o)) * NTOK + n0 + seg * 8;
        float4 x0 = *(const float4*)&x[gidx];
        float4 x1 = *(const float4*)&x[gidx + 4];
        float2 u0 = __bfloat1622float2(*(__nv_bfloat162*)&pv.x);
        float2 u1 = __bfloat1622float2(*(__nv_bfloat162*)&pv.y);
        float2 u2 = __bfloat1622float2(*(__nv_bfloat162*)&pv.z);
        float2 u3 = __bfloat1622float2(*(__nv_bfloat162*)&pv.w);
        float4 o0, o1;
        o0.x = x0.x + gma * (u0.x + bv);
        o0.y = x0.y + gma * (u0.y + bv);
        o0.z = x0.z + gma * (u1.x + bv);
        o0.w = x0.w + gma * (u1.y + bv);
        o1.x = x1.x + gma * (u2.x + bv);
        o1.y = x1.y + gma * (u2.y + bv);
        o1.z = x1.z + gma * (u3.x + bv);
        o1.w = x1.w + gma * (u3.y + bv);
        *(float4*)&out[gidx] = o0;
        *(float4*)&out[gidx + 4] = o1;
    }
}

// ======================= launch =======================
extern "C" void kernel_launch(void* const* d_in, const int* in_sizes, int n_in,
                              void* d_out, int out_size) {
    const float* x  = (const float*)d_in[0];
    const float* gw = (const float*)d_in[1];
    const float* gb = (const float*)d_in[2];
    const float* wq = (const float*)d_in[3];
    const float* bq = (const float*)d_in[4];
    const float* wk = (const float*)d_in[5];
    const float* bk = (const float*)d_in[6];
    const float* wv = (const float*)d_in[7];
    const float* bv = (const float*)d_in[8];
    const float* wo = (const float*)d_in[9];
    const float* bo = (const float*)d_in[10];
    const float* gamma = (const float*)d_in[11];
    float* out = (float*)d_out;

    static bool attr_set = false;
    if (!attr_set) {
        cudaFuncSetAttribute(attn_fused_kernel, cudaFuncAttributeMaxDynamicSharedMemorySize, ATTN_SMEM);
        cudaFuncSetAttribute(fused_qkv_kernel, cudaFuncAttributeMaxDynamicSharedMemorySize, FQ_SMEM);
        attr_set = true;
    }

    gn_stats_kernel<<<BATCH * NGRP, 256>>>(x);
    fused_qkv_kernel<<<dim3(NTOK / 256, BATCH), 256, FQ_SMEM>>>(x, gw, gb, wq, bq, wk, bk, wv, bv);
    attn_fused_kernel<<<dim3(NTOK / 128, BATCH), 256, ATTN_SMEM>>>(x, wo, bo, gamma, out);
}

// round 8
// speedup vs baseline: 11.7464x; 1.0568x over previous
#include <cuda_runtime.h>
#include <cuda_bf16.h>
#include <math.h>
#include <stdint.h>

#define BATCH 8
#define CH 128
#define NTOK 4096
#define NGRP 32
#define CPG 4
#define GN_EPS 1e-5f
#define QK_SCALE 0.08838834764831845f  // 1/sqrt(128)

// ---------------- scratch (device globals; no allocations) ----------------
__device__ float2 g_stats[BATCH * NGRP];             // (mean, rstd) per (b,g)
__device__ __nv_bfloat16 g_q[BATCH * NTOK * CH];     // (b,n,c) token-major, prescaled
__device__ __nv_bfloat16 g_k[BATCH * NTOK * CH];     // (b,n,c) token-major
__device__ __nv_bfloat16 g_v[BATCH * CH * NTOK];     // (b,c,n) channel-major (V^T tiles)

// ======================= helpers =======================
__device__ __forceinline__ uint32_t smem_u32(const void* p) {
    uint32_t a;
    asm("{ .reg .u64 t; cvta.to.shared.u64 t, %1; cvt.u32.u64 %0, t; }" : "=r"(a) : "l"(p));
    return a;
}
__device__ __forceinline__ uint32_t pack_bf16x2(float lo, float hi) {
    uint32_t r;
    asm("cvt.rn.bf16x2.f32 %0, %1, %2;" : "=r"(r) : "f"(hi), "f"(lo));
    return r;
}
// D += A*B, m16n8k16, bf16 in / fp32 accum. A row-major m16xk16, B col-major k16xn8.
__device__ __forceinline__ void mma_bf16(float* d, uint32_t a0, uint32_t a1, uint32_t a2, uint32_t a3,
                                         uint32_t b0, uint32_t b1) {
    asm volatile(
        "mma.sync.aligned.m16n8k16.row.col.f32.bf16.bf16.f32 "
        "{%0,%1,%2,%3}, {%4,%5,%6,%7}, {%8,%9}, {%0,%1,%2,%3};"
        : "+f"(d[0]), "+f"(d[1]), "+f"(d[2]), "+f"(d[3])
        : "r"(a0), "r"(a1), "r"(a2), "r"(a3), "r"(b0), "r"(b1));
}
#define LDSM_X4(r0, r1, r2, r3, addr) \
    asm volatile("ldmatrix.sync.aligned.m8n8.x4.shared.b16 {%0,%1,%2,%3}, [%4];" \
                 : "=r"(r0), "=r"(r1), "=r"(r2), "=r"(r3) : "r"(addr))
#define CP_ASYNC16(dst_u32, src_ptr) \
    asm volatile("cp.async.cg.shared.global [%0], [%1], 16;" :: "r"(dst_u32), "l"(src_ptr))
#define CP_COMMIT()  asm volatile("cp.async.commit_group;" ::: "memory")
#define CP_WAIT1()   asm volatile("cp.async.wait_group 1;" ::: "memory")

// ======================= K1: GroupNorm statistics =======================
__global__ __launch_bounds__(256) void gn_stats_kernel(const float* __restrict__ x) {
    int bg = blockIdx.x;
    size_t base = (size_t)bg * CPG * NTOK;
    const float4* xv = (const float4*)(x + base);
    int tid = threadIdx.x;

    float s = 0.f, ss = 0.f;
#pragma unroll
    for (int r = 0; r < 16; r++) {
        float4 v = xv[tid + r * 256];
        s  += v.x + v.y + v.z + v.w;
        ss += v.x * v.x + v.y * v.y + v.z * v.z + v.w * v.w;
    }
    __shared__ float rs[8], rss[8];
#pragma unroll
    for (int o = 16; o; o >>= 1) {
        s  += __shfl_xor_sync(0xffffffffu, s, o);
        ss += __shfl_xor_sync(0xffffffffu, ss, o);
    }
    if ((tid & 31) == 0) { rs[tid >> 5] = s; rss[tid >> 5] = ss; }
    __syncthreads();
    if (tid == 0) {
        float ts = 0.f, tss = 0.f;
#pragma unroll
        for (int i = 0; i < 8; i++) { ts += rs[i]; tss += rss[i]; }
        const float invN = 1.f / (CPG * NTOK);
        float mean = ts * invN;
        float var  = tss * invN - mean * mean;
        g_stats[bg] = make_float2(mean, rsqrtf(var + GN_EPS));
    }
}

// ======================= K2: fused GN-apply + QKV (128-token tiles, 2 CTA/SM) =======================
#define FQ_XS 0
#define FQ_WS 34816
#define FQ_STG 69632
#define FQ_SMEM 104448

__global__ __launch_bounds__(256, 2) void fused_qkv_kernel(
        const float* __restrict__ x,
        const float* __restrict__ gw, const float* __restrict__ gb,
        const float* __restrict__ wq, const float* __restrict__ bq,
        const float* __restrict__ wk, const float* __restrict__ bk,
        const float* __restrict__ wv, const float* __restrict__ bv) {
    extern __shared__ char smem[];
    uint32_t sbase = smem_u32(smem);
    __nv_bfloat16* xs_h = (__nv_bfloat16*)(smem + FQ_XS);
    uint32_t* ws_u = (uint32_t*)(smem + FQ_WS);
    int tid = threadIdx.x, w = tid >> 5, lid = tid & 31;
    int gr = lid >> 2, t = lid & 3;
    int b = blockIdx.y, n0 = blockIdx.x * 128;
    int o0 = w * 16;

    // ---- load x tile (128 tok), normalize, bf16 into xs [tok][ch] (hw stride 136) ----
#pragma unroll
    for (int r = 0; r < 16; r++) {
        int idx = tid + r * 256;
        int c = idx >> 5, seg = idx & 31;
        float4 v = *(const float4*)&x[((size_t)(b * CH + c)) * NTOK + n0 + seg * 4];
        float2 st = g_stats[b * NGRP + (c >> 2)];
        float a = gw[c] * st.y;
        float bb = gb[c] - st.x * a;
        int tok = seg * 4;
        xs_h[(tok + 0) * 136 + c] = __float2bfloat16(v.x * a + bb);
        xs_h[(tok + 1) * 136 + c] = __float2bfloat16(v.y * a + bb);
        xs_h[(tok + 2) * 136 + c] = __float2bfloat16(v.z * a + bb);
        xs_h[(tok + 3) * 136 + c] = __float2bfloat16(v.w * a + bb);
    }
    __syncthreads();

    for (int p = 0; p < 3; p++) {
        const float* W    = (p == 0) ? wq : (p == 1) ? wk : wv;
        const float* bias = (p == 0) ? bq : (p == 1) ? bk : bv;
        float postscale   = (p == 0) ? QK_SCALE : 1.0f;

        // ---- W -> bf16 smem [o][ch] (stride 68 u32) ----
#pragma unroll
        for (int r = 0; r < 16; r++) {
            int idx = tid + r * 256;
            int o = idx >> 5, seg = idx & 31;
            float4 w4 = *(const float4*)&W[o * 128 + seg * 4];
            uint2 pk;
            pk.x = pack_bf16x2(w4.x, w4.y);
            pk.y = pack_bf16x2(w4.z, w4.w);
            *(uint2*)&ws_u[o * 68 + seg * 2] = pk;
        }
        __syncthreads();

        uint32_t af[8][4];
        {
            uint32_t abase = sbase + FQ_WS + (uint32_t)(o0 + (lid & 15)) * 272 + (uint32_t)(lid >> 4) * 16;
#pragma unroll
            for (int c = 0; c < 8; c++)
                LDSM_X4(af[c][0], af[c][1], af[c][2], af[c][3], abase + c * 32);
        }
        float bias0 = bias[o0 + gr];
        float bias1 = bias[o0 + 8 + gr];

        uint32_t bbase = sbase + FQ_XS + (uint32_t)(lid & 7) * 272 + (uint32_t)(lid >> 3) * 16;
#pragma unroll 4
        for (int nb = 0; nb < 16; nb++) {
            float d[4] = {0.f, 0.f, 0.f, 0.f};
#pragma unroll
            for (int cp = 0; cp < 4; cp++) {
                uint32_t b0, b1, b2, b3;
                LDSM_X4(b0, b1, b2, b3, bbase + (uint32_t)nb * 2176 + cp * 64);
                mma_bf16(d, af[2 * cp][0], af[2 * cp][1], af[2 * cp][2], af[2 * cp][3], b0, b1);
                mma_bf16(d, af[2 * cp + 1][0], af[2 * cp + 1][1], af[2 * cp + 1][2], af[2 * cp + 1][3], b2, b3);
            }
            float v0 = (d[0] + bias0) * postscale;
            float v1 = (d[1] + bias0) * postscale;
            float v2 = (d[2] + bias1) * postscale;
            float v3 = (d[3] + bias1) * postscale;
            if (p == 2) {
                // stage [ch][tok] u32 (stride 68 u32 = 128 tok + pad)
                uint32_t* stg = (uint32_t*)(smem + FQ_STG);
                stg[(o0 + gr) * 68 + nb * 4 + t] = pack_bf16x2(v0, v1);
                stg[(o0 + 8 + gr) * 68 + nb * 4 + t] = pack_bf16x2(v2, v3);
            } else {
                // stage [tok][ch] halfwords (stride 136 hw)
                __nv_bfloat16* stg = (__nv_bfloat16*)(smem + FQ_STG);
                int tok = nb * 8 + 2 * t;
                stg[tok * 136 + o0 + gr] = __float2bfloat16(v0);
                stg[(tok + 1) * 136 + o0 + gr] = __float2bfloat16(v1);
                stg[tok * 136 + o0 + 8 + gr] = __float2bfloat16(v2);
                stg[(tok + 1) * 136 + o0 + 8 + gr] = __float2bfloat16(v3);
            }
        }
        __syncthreads();

        // ---- coalesced copy staging -> global ----
        if (p == 2) {
            // 128 ch rows x 256 B (128 tok bf16) = 16 segs/row, src stride 272 B
#pragma unroll
            for (int r = 0; r < 8; r++) {
                int idx = tid + r * 256;
                int c = idx >> 4, seg = idx & 15;
                uint4 v = *(uint4*)(smem + FQ_STG + c * 272 + seg * 16);
                *(uint4*)((char*)g_v + (((size_t)(b * CH + c)) * NTOK + n0) * 2 + seg * 16) = v;
            }
        } else {
            // 128 tok rows x 256 B (128 ch bf16) = 16 segs/row, src stride 272 B
            __nv_bfloat16* dst = (p == 0) ? g_q : g_k;
#pragma unroll
            for (int r = 0; r < 8; r++) {
                int idx = tid + r * 256;
                int tok = idx >> 4, seg = idx & 15;
                uint4 v = *(uint4*)(smem + FQ_STG + tok * 272 + seg * 16);
                *(uint4*)((char*)dst + ((size_t)b * NTOK + n0 + tok) * 256 + seg * 16) = v;
            }
        }
        __syncthreads();
    }
}

// ======================= K3: flash attention + fused out-proj (3-buffer ring) =======================
#define KT 17408                               // K tile [64 key][136 bf16]
#define VT 18432                               // V^T tile [128 ch][72 bf16]
#define OFF_KB(i) ((i) * KT)
#define OFF_VB(i) (3 * KT + (i) * VT)
#define ATTN_SMEM (3 * KT + 3 * VT)            // 107520 B -> 2 CTA/SM

__global__ __launch_bounds__(256, 2) void attn_fused_kernel(
        const float* __restrict__ x,
        const float* __restrict__ wo, const float* __restrict__ bo,
        const float* __restrict__ gamma, float* __restrict__ out) {
    extern __shared__ char smem[];
    uint32_t sbase = smem_u32(smem);
    int tid = threadIdx.x;
    int w = tid >> 5, lid = tid & 31;
    int gr = lid >> 2, t = lid & 3;
    int r0 = w * 16;
    int b = blockIdx.y, n0 = blockIdx.x * 128;

    const __nv_bfloat16* kg = g_k + (size_t)b * NTOK * CH;
    const __nv_bfloat16* vg = g_v + (size_t)b * CH * NTOK;

    // ---- Q fragments ----
    uint32_t qa[8][4];
    {
        const uint32_t* qu = (const uint32_t*)(g_q + ((size_t)b * NTOK + n0) * CH);
        int row0 = (r0 + gr) * 64, row1 = (r0 + gr + 8) * 64;
#pragma unroll
        for (int k = 0; k < 8; k++) {
            qa[k][0] = qu[row0 + k * 8 + t];
            qa[k][1] = qu[row1 + k * 8 + t];
            qa[k][2] = qu[row0 + k * 8 + t + 4];
            qa[k][3] = qu[row1 + k * 8 + t + 4];
        }
    }

    int kload_row = tid >> 4, kload_seg = tid & 15;    // 16 rows per pass, 4 passes
    int vload_row = tid >> 3, vload_seg = tid & 7;     // 32 rows per pass, 4 passes

    // ---- prologue: tiles 0 and 1 ----
#pragma unroll
    for (int pt = 0; pt < 2; pt++) {
        const char* kn = (const char*)kg + (size_t)pt * 64 * 256;
        const char* vn = (const char*)vg + (size_t)pt * 128;
        uint32_t koff = sbase + OFF_KB(pt);
        uint32_t voff = sbase + OFF_VB(pt);
#pragma unroll
        for (int r = 0; r < 4; r++) {
            int row = kload_row + r * 16;
            CP_ASYNC16(koff + row * 272 + kload_seg * 16, kn + row * 256 + kload_seg * 16);
        }
#pragma unroll
        for (int r = 0; r < 4; r++) {
            int row = vload_row + r * 32;
            CP_ASYNC16(voff + row * 144 + vload_seg * 16, vn + (size_t)row * NTOK * 2 + vload_seg * 16);
        }
        CP_COMMIT();
    }

    float oacc[16][4];
#pragma unroll
    for (int v = 0; v < 16; v++)
#pragma unroll
        for (int i = 0; i < 4; i++) oacc[v][i] = 0.f;
    float l0 = 0.f, l1 = 0.f;

    uint32_t klane = (uint32_t)(lid & 7) * 272 + (uint32_t)(lid >> 3) * 16;
    uint32_t vlane = (uint32_t)(lid & 7) * 144 + (uint32_t)(lid >> 3) * 16;

    int cur = 0, pre = 2;   // ring counters (avoid % in loop)
    for (int tl = 0; tl < NTOK / 64; tl++) {
        CP_WAIT1();
        __syncthreads();     // tile tl ready; buffer `pre` free (last read at tile tl-1)

        // prefetch tile tl+2 into ring slot `pre`
        if (tl + 2 < NTOK / 64) {
            const char* kn = (const char*)kg + (size_t)(tl + 2) * 64 * 256;
            const char* vn = (const char*)vg + (size_t)(tl + 2) * 128;
            uint32_t koff = sbase + OFF_KB(pre);
            uint32_t voff = sbase + OFF_VB(pre);
#pragma unroll
            for (int r = 0; r < 4; r++) {
                int row = kload_row + r * 16;
                CP_ASYNC16(koff + row * 272 + kload_seg * 16, kn + row * 256 + kload_seg * 16);
            }
#pragma unroll
            for (int r = 0; r < 4; r++) {
                int row = vload_row + r * 32;
                CP_ASYNC16(voff + row * 144 + vload_seg * 16, vn + (size_t)row * NTOK * 2 + vload_seg * 16);
            }
        }
        CP_COMMIT();

        uint32_t kb = sbase + OFF_KB(cur) + klane;
        uint32_t vb = sbase + OFF_VB(cur) + vlane;

        // ---- S = Q K^T, exp, pack ----
        uint32_t epk[8][2];
#pragma unroll
        for (int n = 0; n < 8; n++) {
            float sacc[4] = {0.f, 0.f, 0.f, 0.f};
            uint32_t krow = kb + (uint32_t)n * 2176;
#pragma unroll
            for (int cp = 0; cp < 4; cp++) {
                uint32_t b0, b1, b2, b3;
                LDSM_X4(b0, b1, b2, b3, krow + cp * 64);
                mma_bf16(sacc, qa[2 * cp][0], qa[2 * cp][1], qa[2 * cp][2], qa[2 * cp][3], b0, b1);
                mma_bf16(sacc, qa[2 * cp + 1][0], qa[2 * cp + 1][1], qa[2 * cp + 1][2], qa[2 * cp + 1][3], b2, b3);
            }
            float e0 = __expf(sacc[0]);
            float e1 = __expf(sacc[1]);
            float e2 = __expf(sacc[2]);
            float e3 = __expf(sacc[3]);
            l0 += e0 + e1;
            l1 += e2 + e3;
            epk[n][0] = pack_bf16x2(e0, e1);
            epk[n][1] = pack_bf16x2(e2, e3);
        }

        // ---- O += P V ----
#pragma unroll
        for (int up = 0; up < 2; up++) {
            uint32_t a00 = epk[4 * up][0],     a01 = epk[4 * up][1];
            uint32_t a10 = epk[4 * up + 1][0], a11 = epk[4 * up + 1][1];
            uint32_t a20 = epk[4 * up + 2][0], a21 = epk[4 * up + 2][1];
            uint32_t a30 = epk[4 * up + 3][0], a31 = epk[4 * up + 3][1];
#pragma unroll
            for (int v = 0; v < 16; v++) {
                uint32_t b0, b1, b2, b3;
                LDSM_X4(b0, b1, b2, b3, vb + (uint32_t)v * 1152 + up * 64);
                mma_bf16(oacc[v], a00, a01, a10, a11, b0, b1);
                mma_bf16(oacc[v], a20, a21, a30, a31, b2, b3);
            }
        }

        cur = (cur == 2) ? 0 : cur + 1;
        pre = (pre == 2) ? 0 : pre + 1;
    }

    // ---- row sums ----
    l0 += __shfl_xor_sync(0xffffffffu, l0, 1);
    l0 += __shfl_xor_sync(0xffffffffu, l0, 2);
    l1 += __shfl_xor_sync(0xffffffffu, l1, 1);
    l1 += __shfl_xor_sync(0xffffffffu, l1, 2);
    float inv0 = 1.f / l0, inv1 = 1.f / l1;

    // ======== fused output projection epilogue ========
    uint32_t af[8][4];
#pragma unroll
    for (int cp = 0; cp < 8; cp++) {
        af[cp][0] = pack_bf16x2(oacc[2 * cp][0] * inv0,     oacc[2 * cp][1] * inv0);
        af[cp][1] = pack_bf16x2(oacc[2 * cp][2] * inv1,     oacc[2 * cp][3] * inv1);
        af[cp][2] = pack_bf16x2(oacc[2 * cp + 1][0] * inv0, oacc[2 * cp + 1][1] * inv0);
        af[cp][3] = pack_bf16x2(oacc[2 * cp + 1][2] * inv1, oacc[2 * cp + 1][3] * inv1);
    }

    __syncthreads();   // all warps done reading K/V tiles before overwrite

    // Wo -> bf16 smem [o][c] stride 272 B at smem offset 0 (K-ring region)
    {
        uint32_t* wsm = (uint32_t*)smem;
#pragma unroll
        for (int r = 0; r < 16; r++) {
            int idx = tid + r * 256;
            int o = idx >> 5, seg = idx & 31;
            float4 w4 = *(const float4*)&wo[o * 128 + seg * 4];
            wsm[o * 68 + seg * 2]     = pack_bf16x2(w4.x, w4.y);
            wsm[o * 68 + seg * 2 + 1] = pack_bf16x2(w4.z, w4.w);
        }
    }
    __syncthreads();

    // out_p[tok][o], staged bf16 [o][tok] (stride 272 B) in V-ring region
    __nv_bfloat16* stg = (__nv_bfloat16*)(smem + OFF_VB(0));
    uint32_t wob = sbase + klane;
#pragma unroll
    for (int nb = 0; nb < 16; nb++) {
        float d[4] = {0.f, 0.f, 0.f, 0.f};
#pragma unroll
        for (int cp = 0; cp < 4; cp++) {
            uint32_t b0, b1, b2, b3;
            LDSM_X4(b0, b1, b2, b3, wob + (uint32_t)nb * 2176 + cp * 64);
            mma_bf16(d, af[2 * cp][0], af[2 * cp][1], af[2 * cp][2], af[2 * cp][3], b0, b1);
            mma_bf16(d, af[2 * cp + 1][0], af[2 * cp + 1][1], af[2 * cp + 1][2], af[2 * cp + 1][3], b2, b3);
        }
        int o = nb * 8 + 2 * t;
        stg[o * 136 + r0 + gr]           = __float2bfloat16(d[0]);
        stg[(o + 1) * 136 + r0 + gr]     = __float2bfloat16(d[1]);
        stg[o * 136 + r0 + gr + 8]       = __float2bfloat16(d[2]);
        stg[(o + 1) * 136 + r0 + gr + 8] = __float2bfloat16(d[3]);
    }
    __syncthreads();

    // residual + bias + gamma, coalesced fp32 write
    float gma = gamma[0];
#pragma unroll
    for (int r = 0; r < 8; r++) {
        int idx = tid + r * 256;
        int o = idx >> 4, seg = idx & 15;
        uint4 pv = *(uint4*)((char*)stg + o * 272 + seg * 16);
        float bv = bo[o];
        size_t gidx = ((size_t)(b * CH + o)) * NTOK + n0 + seg * 8;
        float4 x0 = *(const float4*)&x[gidx];
        float4 x1 = *(const float4*)&x[gidx + 4];
        float2 u0 = __bfloat1622float2(*(__nv_bfloat162*)&pv.x);
        float2 u1 = __bfloat1622float2(*(__nv_bfloat162*)&pv.y);
        float2 u2 = __bfloat1622float2(*(__nv_bfloat162*)&pv.z);
        float2 u3 = __bfloat1622float2(*(__nv_bfloat162*)&pv.w);
        float4 o0, o1;
        o0.x = x0.x + gma * (u0.x + bv);
        o0.y = x0.y + gma * (u0.y + bv);
        o0.z = x0.z + gma * (u1.x + bv);
        o0.w = x0.w + gma * (u1.y + bv);
        o1.x = x1.x + gma * (u2.x + bv);
        o1.y = x1.y + gma * (u2.y + bv);
        o1.z = x1.z + gma * (u3.x + bv);
        o1.w = x1.w + gma * (u3.y + bv);
        *(float4*)&out[gidx] = o0;
        *(float4*)&out[gidx + 4] = o1;
    }
}

// ======================= launch =======================
extern "C" void kernel_launch(void* const* d_in, const int* in_sizes, int n_in,
                              void* d_out, int out_size) {
    const float* x  = (const float*)d_in[0];
    const float* gw = (const float*)d_in[1];
    const float* gb = (const float*)d_in[2];
    const float* wq = (const float*)d_in[3];
    const float* bq = (const float*)d_in[4];
    const float* wk = (const float*)d_in[5];
    const float* bk = (const float*)d_in[6];
    const float* wv = (const float*)d_in[7];
    const float* bv = (const float*)d_in[8];
    const float* wo = (const float*)d_in[9];
    const float* bo = (const float*)d_in[10];
    const float* gamma = (const float*)d_in[11];
    float* out = (float*)d_out;

    static bool attr_set = false;
    if (!attr_set) {
        cudaFuncSetAttribute(attn_fused_kernel, cudaFuncAttributeMaxDynamicSharedMemorySize, ATTN_SMEM);
        cudaFuncSetAttribute(fused_qkv_kernel, cudaFuncAttributeMaxDynamicSharedMemorySize, FQ_SMEM);
        attr_set = true;
    }

    gn_stats_kernel<<<BATCH * NGRP, 256>>>(x);
    fused_qkv_kernel<<<dim3(NTOK / 128, BATCH), 256, FQ_SMEM>>>(x, gw, gb, wq, bq, wk, bk, wv, bv);
    attn_fused_kernel<<<dim3(NTOK / 128, BATCH), 256, ATTN_SMEM>>>(x, wo, bo, gamma, out);
}